// round 2
// baseline (speedup 1.0000x reference)
#include <cuda_runtime.h>
#include <cstdint>

// ---------------------------------------------------------------------------
// AudioSNN: conv1+spike+pool -> conv2+spike+pool -> fc1 (once) -> 25-step LIF
// fp32 throughout, but using packed f32x2 FFMA2 (PTX fma.rn.f32x2) to double
// MACs/issue. Packing is across independent OUTPUTS, so each output's fp32
// accumulation order is bitwise identical to the round-1 kernel (rel_err 0).
// ---------------------------------------------------------------------------

#define BATCH 1024
#define NSTEPS 25

typedef unsigned long long ull;

__device__ __forceinline__ ull pk2(float lo, float hi) {
    ull r; asm("mov.b64 %0, {%1,%2};" : "=l"(r) : "f"(lo), "f"(hi)); return r;
}
__device__ __forceinline__ ull dup2(float v) { return pk2(v, v); }
__device__ __forceinline__ void fma2(ull& d, ull a, ull b) {
    asm("fma.rn.f32x2 %0, %1, %2, %0;" : "+l"(d) : "l"(a), "l"(b));
}
__device__ __forceinline__ float2 up2(ull v) {
    float2 f; asm("mov.b64 {%0,%1}, %2;" : "=f"(f.x), "=f"(f.y) : "l"(v)); return f;
}

// scratch (device globals: no allocation allowed in kernel_launch)
__device__ float g_c1[BATCH * 32 * 32 * 16];   // pooled spikes after conv1
__device__ float g_xflat[BATCH * 8192];        // pooled spikes after conv2
__device__ float g_cur3[BATCH * 256];          // fc1 output

// ---------------------------------------------------------------------------
// Kernel 1: conv1 (1->32) + spike + pool. Channel-PAIR packed FFMA2.
// ---------------------------------------------------------------------------
__global__ void __launch_bounds__(256) conv1_kernel(const float* __restrict__ x,
                                                    const float* __restrict__ w1,
                                                    const float* __restrict__ b1) {
    __shared__ float sIn[66 * 34];
    __shared__ float2 sWp[16 * 10];   // [chpair][k] = (w[2p][k], w[2p+1][k]), k padded to 10
    __shared__ float sB[32];
    const int t = threadIdx.x;
    const int img = blockIdx.x;

    for (int i = t; i < 66 * 34; i += 256) sIn[i] = 0.f;
    if (t < 288) {
        int ch = t / 9, k = t % 9;
        ((float*)sWp)[((ch >> 1) * 10 + k) * 2 + (ch & 1)] = w1[t];
    }
    if (t < 32) sB[t] = b1[t];
    __syncthreads();

    const float* xi = x + img * 2048;
    for (int i = t; i < 2048; i += 256) {
        int y = i >> 5, xc = i & 31;
        sIn[(y + 1) * 34 + (xc + 1)] = xi[i];
    }
    __syncthreads();

    for (int cellBase = 0; cellBase < 512; cellBase += 256) {
        int cell = cellBase + t;
        int ph = cell >> 4, pw = cell & 15;
        ull ind[4][4];
#pragma unroll
        for (int r = 0; r < 4; r++) {
            const float* ip = sIn + (2 * ph + r) * 34 + 2 * pw;
            float2 p0 = *(const float2*)ip;
            float2 p1 = *(const float2*)(ip + 2);
            ind[r][0] = dup2(p0.x); ind[r][1] = dup2(p0.y);
            ind[r][2] = dup2(p1.x); ind[r][3] = dup2(p1.y);
        }
        for (int chp = 0; chp < 16; chp++) {
            const ull* wp = (const ull*)(sWp + chp * 10);
            ulonglong2 wA = *(const ulonglong2*)wp;
            ulonglong2 wB = *(const ulonglong2*)(wp + 2);
            ulonglong2 wC = *(const ulonglong2*)(wp + 4);
            ulonglong2 wD = *(const ulonglong2*)(wp + 6);
            ull w8 = wp[8];
            float b0 = sB[2 * chp], b1v = sB[2 * chp + 1];
            ull acc[4];
#pragma unroll
            for (int q = 0; q < 4; q++) acc[q] = pk2(b0, b1v);  // bias-first (matches R1 order)
#pragma unroll
            for (int dy = 0; dy < 2; dy++)
#pragma unroll
                for (int dx = 0; dx < 2; dx++) {
                    int q = dy * 2 + dx;
                    fma2(acc[q], wA.x, ind[dy + 0][dx + 0]);
                    fma2(acc[q], wA.y, ind[dy + 0][dx + 1]);
                    fma2(acc[q], wB.x, ind[dy + 0][dx + 2]);
                    fma2(acc[q], wB.y, ind[dy + 1][dx + 0]);
                    fma2(acc[q], wC.x, ind[dy + 1][dx + 1]);
                    fma2(acc[q], wC.y, ind[dy + 1][dx + 2]);
                    fma2(acc[q], wD.x, ind[dy + 2][dx + 0]);
                    fma2(acc[q], wD.y, ind[dy + 2][dx + 1]);
                    fma2(acc[q], w8,   ind[dy + 2][dx + 2]);
                }
            float cnt0 = 0.f, cnt1 = 0.f;
#pragma unroll
            for (int q = 0; q < 4; q++) {
                float2 v = up2(acc[q]);
                cnt0 += (v.x > 1.f) ? 1.f : 0.f;
                cnt1 += (v.y > 1.f) ? 1.f : 0.f;
            }
            g_c1[((img * 32 + 2 * chp) * 32 + ph) * 16 + pw] = cnt0 * 0.25f;
            g_c1[((img * 32 + 2 * chp + 1) * 32 + ph) * 16 + pw] = cnt1 * 0.25f;
        }
    }
}

// ---------------------------------------------------------------------------
// Kernel 2: conv2 (32->64) + spike + pool. Output-channel-PAIR packed FFMA2.
// smem: padded input (78KB) + paired weights (80KB) + bias
// ---------------------------------------------------------------------------
#define C2_SIN   (32 * 34 * 18)          // 19584 floats
#define C2_SWP   (32 * 32 * 10)          // 10240 float2 = 20480 floats
#define C2_SMEM_BYTES ((C2_SIN + 2 * C2_SWP + 64) * 4)

__global__ void __launch_bounds__(256, 1) conv2_kernel(const float* __restrict__ w2,
                                                       const float* __restrict__ b2) {
    extern __shared__ float sm[];
    float* sIn = sm;                            // [ci][34][18]
    float2* sWp = (float2*)(sm + C2_SIN);       // [(pg*32+ci)*10 + k]
    float* sB = sm + C2_SIN + 2 * C2_SWP;       // [64]
    const int t = threadIdx.x;
    const int img = blockIdx.x;

    for (int i = t; i < C2_SIN; i += 256) sIn[i] = 0.f;
    __syncthreads();

    const float* c1p = g_c1 + img * 16384;
    for (int i = t; i < 16384; i += 256) {
        int ci = i >> 9, rem = i & 511;
        int h = rem >> 4, w = rem & 15;
        sIn[ci * 612 + (h + 1) * 18 + (w + 1)] = c1p[i];
    }
    for (int i = t; i < 18432; i += 256) {
        int oc = i / 288, rem = i % 288;
        int ci = rem / 9, k = rem % 9;
        ((float*)sWp)[(((oc >> 1) * 32 + ci) * 10 + k) * 2 + (oc & 1)] = w2[i];
    }
    if (t < 64) sB[t] = b2[t];
    __syncthreads();

    const int cell = t & 127, half = t >> 7;
    const int ph = cell >> 3, pw = cell & 7;
    const int inbase = 2 * ph * 18 + 2 * pw;
    float* xout = g_xflat + img * 8192;

    for (int ocb = 0; ocb < 4; ocb++) {
        const int pgbase = half * 16 + ocb * 4;   // 4 oc-pairs = 8 output channels
        ull acc[4][4];
#pragma unroll
        for (int p = 0; p < 4; p++)
#pragma unroll
            for (int q = 0; q < 4; q++) acc[p][q] = 0ull;

        for (int ci = 0; ci < 32; ci++) {
            const float* ip = sIn + ci * 612 + inbase;
            ull ind[4][4];
#pragma unroll
            for (int r = 0; r < 4; r++) {
                float2 p0 = *(const float2*)(ip + r * 18);
                float2 p1 = *(const float2*)(ip + r * 18 + 2);
                ind[r][0] = dup2(p0.x); ind[r][1] = dup2(p0.y);
                ind[r][2] = dup2(p1.x); ind[r][3] = dup2(p1.y);
            }
#pragma unroll
            for (int p = 0; p < 4; p++) {
                const ull* wp = (const ull*)(sWp + ((pgbase + p) * 32 + ci) * 10);
                ulonglong2 wA = *(const ulonglong2*)wp;
                ulonglong2 wB = *(const ulonglong2*)(wp + 2);
                ulonglong2 wC = *(const ulonglong2*)(wp + 4);
                ulonglong2 wD = *(const ulonglong2*)(wp + 6);
                ull w8 = wp[8];
#pragma unroll
                for (int dy = 0; dy < 2; dy++)
#pragma unroll
                    for (int dx = 0; dx < 2; dx++) {
                        int q = dy * 2 + dx;
                        fma2(acc[p][q], wA.x, ind[dy + 0][dx + 0]);
                        fma2(acc[p][q], wA.y, ind[dy + 0][dx + 1]);
                        fma2(acc[p][q], wB.x, ind[dy + 0][dx + 2]);
                        fma2(acc[p][q], wB.y, ind[dy + 1][dx + 0]);
                        fma2(acc[p][q], wC.x, ind[dy + 1][dx + 1]);
                        fma2(acc[p][q], wC.y, ind[dy + 1][dx + 2]);
                        fma2(acc[p][q], wD.x, ind[dy + 2][dx + 0]);
                        fma2(acc[p][q], wD.y, ind[dy + 2][dx + 1]);
                        fma2(acc[p][q], w8,   ind[dy + 2][dx + 2]);
                    }
            }
        }
#pragma unroll
        for (int p = 0; p < 4; p++) {
            int oc0 = 2 * (pgbase + p);
            float b0 = sB[oc0], b1v = sB[oc0 + 1];
            float cnt0 = 0.f, cnt1 = 0.f;
#pragma unroll
            for (int q = 0; q < 4; q++) {
                float2 v = up2(acc[p][q]);
                cnt0 += (v.x + b0 > 1.f) ? 1.f : 0.f;   // bias-last (matches R1 order)
                cnt1 += (v.y + b1v > 1.f) ? 1.f : 0.f;
            }
            xout[oc0 * 128 + ph * 8 + pw] = cnt0 * 0.25f;
            xout[(oc0 + 1) * 128 + ph * 8 + pw] = cnt1 * 0.25f;
        }
    }
}

// ---------------------------------------------------------------------------
// Kernel 3: fc1 GEMM with col-pair packed FFMA2 + reg double-buffered loads.
// tile 64 rows x 32 cols, grid (16,8) = 128 CTAs, 256 thr, micro 2x4
// ---------------------------------------------------------------------------
__global__ void __launch_bounds__(256) fc1_kernel(const float* __restrict__ W,
                                                  const float* __restrict__ bias) {
    __shared__ float2 sA2[64][64];   // [k][row], value duplicated in both lanes
    __shared__ float2 sWp[64][16];   // [k][colpair] = (W[n][k], W[n+1][k])
    const int t = threadIdx.x;
    const int row0 = blockIdx.x * 64;
    const int n0 = blockIdx.y * 32;
    const int ty = t >> 3;           // 0..31 -> rows 2ty, 2ty+1
    const int tx = t & 7;            // cols 4tx..4tx+3 (pairs 2tx, 2tx+1)

    const int lr = t >> 2, lk4 = (t & 3) * 16;   // A loader
    const int wn = t >> 3, wk = (t & 7) * 8;     // W loader

    ull acc[2][2] = {{0ull, 0ull}, {0ull, 0ull}};
    float4 ra[4], rw[2];

    const float* Arow = g_xflat + (row0 + lr) * 8192;
    const float* Wrow = W + (n0 + wn) * 8192;

#pragma unroll
    for (int j = 0; j < 4; j++) ra[j] = *(const float4*)(Arow + lk4 + 4 * j);
#pragma unroll
    for (int j = 0; j < 2; j++) rw[j] = *(const float4*)(Wrow + wk + 4 * j);

    for (int k0 = 0; k0 < 8192; k0 += 64) {
        // stage prefetched regs -> smem
#pragma unroll
        for (int j = 0; j < 4; j++) {
            int k = lk4 + 4 * j;
            sA2[k + 0][lr] = make_float2(ra[j].x, ra[j].x);
            sA2[k + 1][lr] = make_float2(ra[j].y, ra[j].y);
            sA2[k + 2][lr] = make_float2(ra[j].z, ra[j].z);
            sA2[k + 3][lr] = make_float2(ra[j].w, ra[j].w);
        }
        {
            float* wf = (float*)sWp;
            int p = wn >> 1, sel = wn & 1;
#pragma unroll
            for (int j = 0; j < 2; j++) {
                int k = wk + 4 * j;
                wf[((k + 0) * 16 + p) * 2 + sel] = rw[j].x;
                wf[((k + 1) * 16 + p) * 2 + sel] = rw[j].y;
                wf[((k + 2) * 16 + p) * 2 + sel] = rw[j].z;
                wf[((k + 3) * 16 + p) * 2 + sel] = rw[j].w;
            }
        }
        __syncthreads();

        if (k0 + 64 < 8192) {
#pragma unroll
            for (int j = 0; j < 4; j++) ra[j] = *(const float4*)(Arow + k0 + 64 + lk4 + 4 * j);
#pragma unroll
            for (int j = 0; j < 2; j++) rw[j] = *(const float4*)(Wrow + k0 + 64 + wk + 4 * j);
        }

#pragma unroll 8
        for (int k = 0; k < 64; k++) {
            ull a0 = *(const ull*)&sA2[k][2 * ty];
            ull a1 = *(const ull*)&sA2[k][2 * ty + 1];
            ulonglong2 w = *(const ulonglong2*)&sWp[k][2 * tx];
            fma2(acc[0][0], a0, w.x); fma2(acc[0][1], a0, w.y);
            fma2(acc[1][0], a1, w.x); fma2(acc[1][1], a1, w.y);
        }
        __syncthreads();
    }

#pragma unroll
    for (int rl = 0; rl < 2; rl++) {
        int row = row0 + 2 * ty + rl;
#pragma unroll
        for (int p = 0; p < 2; p++) {
            float2 v = up2(acc[rl][p]);
            int n = n0 + 4 * tx + 2 * p;
            g_cur3[row * 256 + n]     = v.x + bias[n];
            g_cur3[row * 256 + n + 1] = v.y + bias[n + 1];
        }
    }
}

// ---------------------------------------------------------------------------
// Kernel 4: 25-step LIF recurrence; layer-4 GEMV uses row-packed FFMA2
// (spike pairs come free from ulonglong2 view of the float4 in smem).
// ---------------------------------------------------------------------------
#define REC_W2S (256 * 129)
#define REC_SMEM_BYTES ((REC_W2S + 1280 + 128 + 16 + 2048 + 1024) * 4)

__global__ void __launch_bounds__(256, 1) rec_kernel(const float* __restrict__ w2,
                                                     const float* __restrict__ b2,
                                                     const float* __restrict__ w3,
                                                     const float* __restrict__ b3,
                                                     float* __restrict__ out) {
    extern __shared__ float sm[];
    float* w2s   = sm;                 // [i*129 + j]
    float* w3s   = w2s + REC_W2S;      // [k*10 + j]
    float* b2s   = w3s + 1280;
    float* b3s   = b2s + 128;
    float* spk3s = b3s + 16;           // [256][8]
    float* spk4s = spk3s + 2048;       // [128][8]

    const int t = threadIdx.x;
    const int rowbase = blockIdx.x * 8;

    for (int idx = t; idx < 128 * 256; idx += 256) {
        int j = idx >> 8, i = idx & 255;
        w2s[i * 129 + j] = w2[idx];
    }
    for (int idx = t; idx < 1280; idx += 256) {
        int j = idx >> 7, k = idx & 127;
        w3s[k * 10 + j] = w3[idx];
    }
    if (t < 128) b2s[t] = b2[t];
    if (t < 10)  b3s[t] = b3[t];
    __syncthreads();

    float mem3[8], c3[8];
#pragma unroll
    for (int r = 0; r < 8; r++) {
        mem3[r] = 0.f;
        c3[r] = g_cur3[(rowbase + r) * 256 + t];
    }
    const int j4 = t & 127, rg = t >> 7;
    float mem4[4] = {0.f, 0.f, 0.f, 0.f};
    const float b2v = b2s[j4];
    float mem5 = 0.f;
    const int r5 = t / 10, j5 = t % 10;
    const float b3v = (t < 80) ? b3s[j5] : 0.f;

    for (int step = 0; step < NSTEPS; step++) {
        // layer 3 LIF
#pragma unroll
        for (int r = 0; r < 8; r++) {
            float reset = (mem3[r] > 1.f) ? 1.f : 0.f;
            float m = 0.95f * mem3[r] + c3[r] - reset;
            mem3[r] = m;
            spk3s[t * 8 + r] = (m > 1.f) ? 1.f : 0.f;
        }
        __syncthreads();

        // layer 4: cur4 = spk3 @ w2^T + b2 (packed over row pairs)
        ull a01 = pk2(b2v, b2v), a23 = a01;   // wait: per-row bias -> both lanes = b2v, ok
#pragma unroll 8
        for (int i = 0; i < 256; i++) {
            ull wd = dup2(w2s[i * 129 + j4]);
            ulonglong2 s = *(const ulonglong2*)&spk3s[i * 8 + rg * 4];
            fma2(a01, wd, s.x);
            fma2(a23, wd, s.y);
        }
        {
            float2 v01 = up2(a01), v23 = up2(a23);
            float a4[4] = {v01.x, v01.y, v23.x, v23.y};
#pragma unroll
            for (int r = 0; r < 4; r++) {
                float reset = (mem4[r] > 1.f) ? 1.f : 0.f;
                float m = 0.95f * mem4[r] + a4[r] - reset;
                mem4[r] = m;
                spk4s[j4 * 8 + rg * 4 + r] = (m > 1.f) ? 1.f : 0.f;
            }
        }
        __syncthreads();

        // layer 5
        if (t < 80) {
            float a5 = b3v;
#pragma unroll 8
            for (int k = 0; k < 128; k++)
                a5 += w3s[k * 10 + j5] * spk4s[k * 8 + r5];
            float reset = (mem5 > 1.f) ? 1.f : 0.f;
            float m = 0.95f * mem5 + a5 - reset;
            mem5 = m;
            out[(step * 1024 + rowbase + r5) * 10 + j5] = (m > 1.f) ? 1.f : 0.f;
        }
        __syncthreads();
    }
}

// ---------------------------------------------------------------------------
extern "C" void kernel_launch(void* const* d_in, const int* in_sizes, int n_in,
                              void* d_out, int out_size) {
    const float* x       = (const float*)d_in[0];
    const float* conv1_w = (const float*)d_in[1];
    const float* conv1_b = (const float*)d_in[2];
    const float* conv2_w = (const float*)d_in[3];
    const float* conv2_b = (const float*)d_in[4];
    const float* fc1_w   = (const float*)d_in[5];
    const float* fc1_b   = (const float*)d_in[6];
    const float* fc2_w   = (const float*)d_in[7];
    const float* fc2_b   = (const float*)d_in[8];
    const float* fc3_w   = (const float*)d_in[9];
    const float* fc3_b   = (const float*)d_in[10];
    float* out = (float*)d_out;

    cudaFuncSetAttribute(conv2_kernel, cudaFuncAttributeMaxDynamicSharedMemorySize,
                         C2_SMEM_BYTES);
    cudaFuncSetAttribute(rec_kernel, cudaFuncAttributeMaxDynamicSharedMemorySize,
                         REC_SMEM_BYTES);

    conv1_kernel<<<BATCH, 256>>>(x, conv1_w, conv1_b);
    conv2_kernel<<<BATCH, 256, C2_SMEM_BYTES>>>(conv2_w, conv2_b);
    fc1_kernel<<<dim3(16, 8), 256>>>(fc1_w, fc1_b);
    rec_kernel<<<128, 256, REC_SMEM_BYTES>>>(fc2_w, fc2_b, fc3_w, fc3_b, out);
}

// round 4
// speedup vs baseline: 1.2159x; 1.2159x over previous
#include <cuda_runtime.h>
#include <cuda_bf16.h>
#include <cstdint>

#define BATCH 1024
#define NSTEPS 25

// scratch
__device__ float g_c1[BATCH * 32 * 32 * 16];
__device__ float g_xflat[BATCH * 8192];
__device__ float g_cur3[BATCH * 256];

// ---------------------------------------------------------------------------
// mma.sync m16n8k16 bf16 (baseline PTX, works on compute_103)
// ---------------------------------------------------------------------------
__device__ __forceinline__ void mma_bf16(float* d, const uint32_t* a, const uint32_t* b) {
    asm volatile(
        "mma.sync.aligned.m16n8k16.row.col.f32.bf16.bf16.f32 "
        "{%0,%1,%2,%3}, {%4,%5,%6,%7}, {%8,%9}, {%0,%1,%2,%3};"
        : "+f"(d[0]), "+f"(d[1]), "+f"(d[2]), "+f"(d[3])
        : "r"(a[0]), "r"(a[1]), "r"(a[2]), "r"(a[3]), "r"(b[0]), "r"(b[1]));
}

// ---------------------------------------------------------------------------
// Kernel 1: conv1 (1->32, 3x3 SAME) + spike + pool  (proven R1 version)
// ---------------------------------------------------------------------------
__global__ void __launch_bounds__(256) conv1_kernel(const float* __restrict__ x,
                                                    const float* __restrict__ w1,
                                                    const float* __restrict__ b1) {
    __shared__ float sIn[66 * 34];
    __shared__ float sW[32 * 9];
    __shared__ float sB[32];
    const int t = threadIdx.x;
    const int img = blockIdx.x;

    for (int i = t; i < 66 * 34; i += 256) sIn[i] = 0.f;
    for (int i = t; i < 288; i += 256) sW[i] = w1[i];
    if (t < 32) sB[t] = b1[t];
    __syncthreads();

    const float* xi = x + img * 2048;
    for (int i = t; i < 2048; i += 256) {
        int y = i >> 5, xc = i & 31;
        sIn[(y + 1) * 34 + (xc + 1)] = xi[i];
    }
    __syncthreads();

    for (int cellBase = 0; cellBase < 512; cellBase += 256) {
        int cell = cellBase + t;
        int ph = cell >> 4, pw = cell & 15;
        float in[4][4];
#pragma unroll
        for (int r = 0; r < 4; r++)
#pragma unroll
            for (int c = 0; c < 4; c++)
                in[r][c] = sIn[(2 * ph + r) * 34 + (2 * pw + c)];

        for (int ch = 0; ch < 32; ch++) {
            float wv[9];
#pragma unroll
            for (int k = 0; k < 9; k++) wv[k] = sW[ch * 9 + k];
            float bb = sB[ch];
            float cnt = 0.f;
#pragma unroll
            for (int dy = 0; dy < 2; dy++)
#pragma unroll
                for (int dx = 0; dx < 2; dx++) {
                    float s = bb;
#pragma unroll
                    for (int ky = 0; ky < 3; ky++)
#pragma unroll
                        for (int kx = 0; kx < 3; kx++)
                            s += wv[ky * 3 + kx] * in[dy + ky][dx + kx];
                    cnt += (s > 1.f) ? 1.f : 0.f;
                }
            g_c1[((img * 32 + ch) * 32 + ph) * 16 + pw] = cnt * 0.25f;
        }
    }
}

// ---------------------------------------------------------------------------
// Kernel 2: conv2 via mma.sync bf16, 3-split weights.
//   M = 64 output channels, N = 512 positions, K = 288 (18 k16-steps) x 3.
//   A frags (weights) prebuilt in smem in per-lane fragment layout.
//   B frags (im2col) built per k-step into a double buffer, from a haloed
//   bf16 input copy (no bounds checks). Pooling is entirely in-thread.
// ---------------------------------------------------------------------------
#define C2_AF_BYTES 110592              // 3*4*18*32*4 u32
#define C2_BF_BYTES 32768               // 2 * 4096 u32
#define C2_IN_BYTES 39168               // 32*34*18 bf16
#define C2_SMEM (C2_AF_BYTES + C2_BF_BYTES + C2_IN_BYTES + 1152 + 256)

__global__ void __launch_bounds__(256, 1) conv2_mma(const float* __restrict__ w2,
                                                    const float* __restrict__ b2) {
    extern __shared__ char sm[];
    uint32_t* sAf = (uint32_t*)sm;                               // weight frags
    uint32_t* sBf = (uint32_t*)(sm + C2_AF_BYTES);               // im2col frags x2
    __nv_bfloat16* sIn = (__nv_bfloat16*)(sm + C2_AF_BYTES + C2_BF_BYTES);
    int* ktab = (int*)(sm + C2_AF_BYTES + C2_BF_BYTES + C2_IN_BYTES);
    float* sB = (float*)(sm + C2_AF_BYTES + C2_BF_BYTES + C2_IN_BYTES + 1152);

    const int t = threadIdx.x;
    const int lane = t & 31, wid = t >> 5;

    // ktab: k -> offset into haloed input [ci][34][18]
    for (int k = t; k < 288; k += 256) {
        int ci = k / 9, tap = k % 9;
        ktab[k] = ci * 612 + (tap / 3) * 18 + (tap % 3);
    }
    if (t < 64) sB[t] = b2[t];
    // clear input (incl. halo) once; interior overwritten per image
    for (int i = t; i < 9792; i += 256) ((uint32_t*)sIn)[i] = 0u;

    // build weight fragments, 3 splits
    for (int idx = t; idx < 4 * 18 * 32 * 4; idx += 256) {
        int r = idx & 3, ln = (idx >> 2) & 31, ks = (idx >> 7) % 18, mt = idx / (128 * 18);
        int row = mt * 16 + (ln >> 2) + (r & 1) * 8;
        int col = ks * 16 + (ln & 3) * 2 + (r >> 1) * 8;
        float w0 = w2[row * 288 + col], w1v = w2[row * 288 + col + 1];
#pragma unroll
        for (int s = 0; s < 3; s++) {
            __nv_bfloat16 h0 = __float2bfloat16(w0);
            __nv_bfloat16 h1 = __float2bfloat16(w1v);
            w0 -= __bfloat162float(h0);
            w1v -= __bfloat162float(h1);
            sAf[((s * 4 + mt) * 18 + ks) * 128 + ln * 4 + r] =
                (uint32_t)*(uint16_t*)&h0 | ((uint32_t)*(uint16_t*)&h1 << 16);
        }
    }
    __syncthreads();

    float biasr[4][2];
#pragma unroll
    for (int mt = 0; mt < 4; mt++) {
        biasr[mt][0] = sB[mt * 16 + (lane >> 2)];
        biasr[mt][1] = sB[mt * 16 + (lane >> 2) + 8];
    }

    // build-thread position mapping (B-fragment lane layout)
    const int nb = (t >> 2) * 8 + (t & 3) * 2;
    const int hw0 = (nb >> 4) * 18 + (nb & 15);
    const int hw1 = ((nb + 1) >> 4) * 18 + ((nb + 1) & 15);

    for (int img = blockIdx.x; img < BATCH; img += gridDim.x) {
        // stage input as bf16 with halo
        const float* in = g_c1 + img * 16384;
        for (int i = t; i < 4096; i += 256) {
            float4 v = ((const float4*)in)[i];
            int e = i * 4, ci = e >> 9, rem = e & 511, h = rem >> 4, w = rem & 15;
            __nv_bfloat16* p = sIn + ci * 612 + (h + 1) * 18 + (w + 1);
            p[0] = __float2bfloat16(v.x); p[1] = __float2bfloat16(v.y);
            p[2] = __float2bfloat16(v.z); p[3] = __float2bfloat16(v.w);
        }
        __syncthreads();

        float acc[4][8][4];
#pragma unroll
        for (int mt = 0; mt < 4; mt++)
#pragma unroll
            for (int nt = 0; nt < 8; nt++)
#pragma unroll
                for (int q = 0; q < 4; q++) acc[mt][nt][q] = 0.f;

        for (int ks = 0; ks < 18; ks++) {
            // ---- build B fragments for this k-step ----
            int kt[16];
#pragma unroll
            for (int q4 = 0; q4 < 4; q4++) {
                int4 v = ((const int4*)(ktab + ks * 16))[q4];
                kt[q4 * 4] = v.x; kt[q4 * 4 + 1] = v.y;
                kt[q4 * 4 + 2] = v.z; kt[q4 * 4 + 3] = v.w;
            }
            uint32_t* dst = sBf + (ks & 1) * 4096 + t * 16;
#pragma unroll
            for (int q = 0; q < 16; q++) {
                int jreg = q & 1, tig = (q >> 1) & 3;
                int hw = (q >> 3) ? hw1 : hw0;
                int k0 = tig * 2 + jreg * 8;
                uint32_t lo = *(const uint16_t*)(sIn + kt[k0] + hw);
                uint32_t hi = *(const uint16_t*)(sIn + kt[k0 + 1] + hw);
                dst[q] = lo | (hi << 16);
            }
            __syncthreads();

            // ---- consume: load B frags, loop splits x mtiles ----
            const uint32_t* bsrc = sBf + (ks & 1) * 4096;
            uint32_t bfr[8][2];
#pragma unroll
            for (int nt = 0; nt < 8; nt++) {
                uint2 v = *(const uint2*)(bsrc + (wid * 8 + nt) * 64 + lane * 2);
                bfr[nt][0] = v.x; bfr[nt][1] = v.y;
            }
#pragma unroll
            for (int s = 0; s < 3; s++)
#pragma unroll
                for (int mt = 0; mt < 4; mt++) {
                    uint4 av = ((const uint4*)(sAf + ((s * 4 + mt) * 18 + ks) * 128))[lane];
                    uint32_t a[4] = {av.x, av.y, av.z, av.w};
#pragma unroll
                    for (int nt = 0; nt < 8; nt++)
                        mma_bf16(acc[mt][nt], a, bfr[nt]);
                }
        }

        // ---- epilogue: +bias, spike, in-thread 2x2 pool ----
        float* xout = g_xflat + img * 8192;
#pragma unroll
        for (int mt = 0; mt < 4; mt++)
#pragma unroll
            for (int rh = 0; rh < 2; rh++) {
                int ch = mt * 16 + (lane >> 2) + rh * 8;
                float bv = biasr[mt][rh];
#pragma unroll
                for (int np = 0; np < 4; np++) {
                    int nt = (np & 1) + (np >> 1) * 4;   // {0,1,4,5}
                    float s0 = (acc[mt][nt][rh * 2]     + bv > 1.f) ? 1.f : 0.f;
                    float s1 = (acc[mt][nt][rh * 2 + 1] + bv > 1.f) ? 1.f : 0.f;
                    float s2 = (acc[mt][nt + 2][rh * 2]     + bv > 1.f) ? 1.f : 0.f;
                    float s3 = (acc[mt][nt + 2][rh * 2 + 1] + bv > 1.f) ? 1.f : 0.f;
                    int h = wid * 4 + (nt >> 1);         // even
                    int ph = h >> 1;
                    int pw = (nt & 1) * 4 + (lane & 3);
                    xout[ch * 128 + ph * 8 + pw] = (s0 + s1 + s2 + s3) * 0.25f;
                }
            }
        __syncthreads();   // before next image overwrites sIn
    }
}

// ---------------------------------------------------------------------------
// Kernel 3: fc1 GEMM (proven R1 version)
// ---------------------------------------------------------------------------
__global__ void __launch_bounds__(256) fc1_kernel(const float* __restrict__ W,
                                                  const float* __restrict__ bias) {
    __shared__ float sA[64][64];
    __shared__ float sW2[64][32];
    const int t = threadIdx.x;
    const int row0 = blockIdx.x * 64;
    const int n0 = blockIdx.y * 32;
    const int tx = t & 15, ty = t >> 4;

    const int lr = t >> 2, lk = (t & 3) * 16;
    const int wn = t >> 3, wk = (t & 7) * 8;

    float acc[4][2];
#pragma unroll
    for (int r = 0; r < 4; r++) { acc[r][0] = 0.f; acc[r][1] = 0.f; }

    for (int k0 = 0; k0 < 8192; k0 += 64) {
#pragma unroll
        for (int j = 0; j < 4; j++) {
            float4 v = *(const float4*)&g_xflat[(row0 + lr) * 8192 + k0 + lk + 4 * j];
            sA[lk + 4 * j + 0][lr] = v.x;
            sA[lk + 4 * j + 1][lr] = v.y;
            sA[lk + 4 * j + 2][lr] = v.z;
            sA[lk + 4 * j + 3][lr] = v.w;
        }
#pragma unroll
        for (int j = 0; j < 2; j++) {
            float4 v = *(const float4*)&W[(n0 + wn) * 8192 + k0 + wk + 4 * j];
            sW2[wk + 4 * j + 0][wn] = v.x;
            sW2[wk + 4 * j + 1][wn] = v.y;
            sW2[wk + 4 * j + 2][wn] = v.z;
            sW2[wk + 4 * j + 3][wn] = v.w;
        }
        __syncthreads();
#pragma unroll
        for (int k = 0; k < 64; k++) {
            float4 a = *(const float4*)&sA[k][ty * 4];
            float2 w = *(const float2*)&sW2[k][tx * 2];
            acc[0][0] += a.x * w.x; acc[0][1] += a.x * w.y;
            acc[1][0] += a.y * w.x; acc[1][1] += a.y * w.y;
            acc[2][0] += a.z * w.x; acc[2][1] += a.z * w.y;
            acc[3][0] += a.w * w.x; acc[3][1] += a.w * w.y;
        }
        __syncthreads();
    }
#pragma unroll
    for (int r = 0; r < 4; r++)
#pragma unroll
        for (int c = 0; c < 2; c++)
            g_cur3[(row0 + ty * 4 + r) * 256 + n0 + tx * 2 + c] =
                acc[r][c] + bias[n0 + tx * 2 + c];
}

// ---------------------------------------------------------------------------
// Kernel 4: 25-step LIF recurrence (proven R1 version)
// ---------------------------------------------------------------------------
#define REC_W2S (256 * 129)
#define REC_SMEM_BYTES ((REC_W2S + 1280 + 128 + 16 + 2048 + 1024) * 4)

__global__ void __launch_bounds__(256, 1) rec_kernel(const float* __restrict__ w2,
                                                     const float* __restrict__ b2,
                                                     const float* __restrict__ w3,
                                                     const float* __restrict__ b3,
                                                     float* __restrict__ out) {
    extern __shared__ float smr[];
    float* w2s   = smr;
    float* w3s   = w2s + REC_W2S;
    float* b2s   = w3s + 1280;
    float* b3s   = b2s + 128;
    float* spk3s = b3s + 16;
    float* spk4s = spk3s + 2048;

    const int t = threadIdx.x;
    const int rowbase = blockIdx.x * 8;

    for (int idx = t; idx < 128 * 256; idx += 256) {
        int j = idx >> 8, i = idx & 255;
        w2s[i * 129 + j] = w2[idx];
    }
    for (int idx = t; idx < 1280; idx += 256) {
        int j = idx >> 7, k = idx & 127;
        w3s[k * 10 + j] = w3[idx];
    }
    if (t < 128) b2s[t] = b2[t];
    if (t < 10)  b3s[t] = b3[t];
    __syncthreads();

    float mem3[8], c3[8];
#pragma unroll
    for (int r = 0; r < 8; r++) {
        mem3[r] = 0.f;
        c3[r] = g_cur3[(rowbase + r) * 256 + t];
    }
    const int j4 = t & 127, rg = t >> 7;
    float mem4[4] = {0.f, 0.f, 0.f, 0.f};
    const float b2v = b2s[j4];
    float mem5 = 0.f;
    const int r5 = t / 10, j5 = t % 10;
    const float b3v = (t < 80) ? b3s[j5] : 0.f;

    for (int step = 0; step < NSTEPS; step++) {
#pragma unroll
        for (int r = 0; r < 8; r++) {
            float reset = (mem3[r] > 1.f) ? 1.f : 0.f;
            float m = 0.95f * mem3[r] + c3[r] - reset;
            mem3[r] = m;
            spk3s[t * 8 + r] = (m > 1.f) ? 1.f : 0.f;
        }
        __syncthreads();

        float a4[4];
#pragma unroll
        for (int r = 0; r < 4; r++) a4[r] = b2v;
#pragma unroll 4
        for (int i = 0; i < 256; i++) {
            float w = w2s[i * 129 + j4];
            float4 s = *(const float4*)&spk3s[i * 8 + rg * 4];
            a4[0] += w * s.x; a4[1] += w * s.y; a4[2] += w * s.z; a4[3] += w * s.w;
        }
#pragma unroll
        for (int r = 0; r < 4; r++) {
            float reset = (mem4[r] > 1.f) ? 1.f : 0.f;
            float m = 0.95f * mem4[r] + a4[r] - reset;
            mem4[r] = m;
            spk4s[j4 * 8 + rg * 4 + r] = (m > 1.f) ? 1.f : 0.f;
        }
        __syncthreads();

        if (t < 80) {
            float a5 = b3v;
#pragma unroll 8
            for (int k = 0; k < 128; k++)
                a5 += w3s[k * 10 + j5] * spk4s[k * 8 + r5];
            float reset = (mem5 > 1.f) ? 1.f : 0.f;
            float m = 0.95f * mem5 + a5 - reset;
            mem5 = m;
            out[(step * 1024 + rowbase + r5) * 10 + j5] = (m > 1.f) ? 1.f : 0.f;
        }
        __syncthreads();
    }
}

// ---------------------------------------------------------------------------
extern "C" void kernel_launch(void* const* d_in, const int* in_sizes, int n_in,
                              void* d_out, int out_size) {
    const float* x       = (const float*)d_in[0];
    const float* conv1_w = (const float*)d_in[1];
    const float* conv1_b = (const float*)d_in[2];
    const float* conv2_w = (const float*)d_in[3];
    const float* conv2_b = (const float*)d_in[4];
    const float* fc1_w   = (const float*)d_in[5];
    const float* fc1_b   = (const float*)d_in[6];
    const float* fc2_w   = (const float*)d_in[7];
    const float* fc2_b   = (const float*)d_in[8];
    const float* fc3_w   = (const float*)d_in[9];
    const float* fc3_b   = (const float*)d_in[10];
    float* out = (float*)d_out;

    cudaFuncSetAttribute(conv2_mma, cudaFuncAttributeMaxDynamicSharedMemorySize,
                         C2_SMEM);
    cudaFuncSetAttribute(rec_kernel, cudaFuncAttributeMaxDynamicSharedMemorySize,
                         REC_SMEM_BYTES);

    conv1_kernel<<<BATCH, 256>>>(x, conv1_w, conv1_b);
    conv2_mma<<<148, 256, C2_SMEM>>>(conv2_w, conv2_b);
    fc1_kernel<<<dim3(16, 8), 256>>>(fc1_w, fc1_b);
    rec_kernel<<<128, 256, REC_SMEM_BYTES>>>(fc2_w, fc2_b, fc3_w, fc3_b, out);
}

// round 5
// speedup vs baseline: 1.5012x; 1.2346x over previous
#include <cuda_runtime.h>
#include <cuda_bf16.h>
#include <cstdint>

#define BATCH 1024
#define NSTEPS 25

// scratch
__device__ float g_c1[BATCH * 32 * 32 * 16];
__device__ float g_xflat[BATCH * 8192];
__device__ float g_cur3[BATCH * 256];

// ---------------------------------------------------------------------------
// mma.sync m16n8k16 bf16 (baseline PTX, works on compute_103)
// ---------------------------------------------------------------------------
__device__ __forceinline__ void mma_bf16(float* d, const uint32_t* a, const uint32_t* b) {
    asm volatile(
        "mma.sync.aligned.m16n8k16.row.col.f32.bf16.bf16.f32 "
        "{%0,%1,%2,%3}, {%4,%5,%6,%7}, {%8,%9}, {%0,%1,%2,%3};"
        : "+f"(d[0]), "+f"(d[1]), "+f"(d[2]), "+f"(d[3])
        : "r"(a[0]), "r"(a[1]), "r"(a[2]), "r"(a[3]), "r"(b[0]), "r"(b[1]));
}

// ---------------------------------------------------------------------------
// Kernel 1: conv1 (1->32, 3x3 SAME) + spike + pool  (proven R1 version)
// ---------------------------------------------------------------------------
__global__ void __launch_bounds__(256) conv1_kernel(const float* __restrict__ x,
                                                    const float* __restrict__ w1,
                                                    const float* __restrict__ b1) {
    __shared__ float sIn[66 * 34];
    __shared__ float sW[32 * 9];
    __shared__ float sB[32];
    const int t = threadIdx.x;
    const int img = blockIdx.x;

    for (int i = t; i < 66 * 34; i += 256) sIn[i] = 0.f;
    for (int i = t; i < 288; i += 256) sW[i] = w1[i];
    if (t < 32) sB[t] = b1[t];
    __syncthreads();

    const float* xi = x + img * 2048;
    for (int i = t; i < 2048; i += 256) {
        int y = i >> 5, xc = i & 31;
        sIn[(y + 1) * 34 + (xc + 1)] = xi[i];
    }
    __syncthreads();

    for (int cellBase = 0; cellBase < 512; cellBase += 256) {
        int cell = cellBase + t;
        int ph = cell >> 4, pw = cell & 15;
        float in[4][4];
#pragma unroll
        for (int r = 0; r < 4; r++)
#pragma unroll
            for (int c = 0; c < 4; c++)
                in[r][c] = sIn[(2 * ph + r) * 34 + (2 * pw + c)];

        for (int ch = 0; ch < 32; ch++) {
            float wv[9];
#pragma unroll
            for (int k = 0; k < 9; k++) wv[k] = sW[ch * 9 + k];
            float bb = sB[ch];
            float cnt = 0.f;
#pragma unroll
            for (int dy = 0; dy < 2; dy++)
#pragma unroll
                for (int dx = 0; dx < 2; dx++) {
                    float s = bb;
#pragma unroll
                    for (int ky = 0; ky < 3; ky++)
#pragma unroll
                        for (int kx = 0; kx < 3; kx++)
                            s += wv[ky * 3 + kx] * in[dy + ky][dx + kx];
                    cnt += (s > 1.f) ? 1.f : 0.f;
                }
            g_c1[((img * 32 + ch) * 32 + ph) * 16 + pw] = cnt * 0.25f;
        }
    }
}

// ---------------------------------------------------------------------------
// Kernel 2: conv2 via mma.sync bf16 3-split, channel-last staged input,
//   direct per-lane B loads (no fragment build pass, no per-k-step syncs).
//   K order: ks = tap*2 + cichunk; k within chunk = ci.
//   Input staged as [h(34)][w(18)][ci pad 40] bf16 (conflict-free B loads).
// ---------------------------------------------------------------------------
#define C2_AF_BYTES 110592                    // 3*4*18*128 u32
#define C2_IN_BYTES 48960                     // 34*18*40 bf16
#define C2_SMEM (C2_AF_BYTES + C2_IN_BYTES + 256)

__global__ void __launch_bounds__(256, 1) conv2_mma(const float* __restrict__ w2,
                                                    const float* __restrict__ b2) {
    extern __shared__ char sm[];
    uint32_t* sAf = (uint32_t*)sm;
    __nv_bfloat16* sIn = (__nv_bfloat16*)(sm + C2_AF_BYTES);
    float* sB = (float*)(sm + C2_AF_BYTES + C2_IN_BYTES);

    const int t = threadIdx.x;
    const int lane = t & 31, wid = t >> 5;

    if (t < 64) sB[t] = b2[t];
    // zero staged input once (halo stays zero; interior rewritten per image)
    for (int i = t; i < C2_IN_BYTES / 4; i += 256) ((uint32_t*)sIn)[i] = 0u;

    // build weight fragments, 3 splits, K order (tap, ci)
    for (int idx = t; idx < 4 * 18 * 32 * 4; idx += 256) {
        int r = idx & 3, ln = (idx >> 2) & 31, ks = (idx >> 7) % 18, mt = idx / (128 * 18);
        int oc = mt * 16 + (ln >> 2) + (r & 1) * 8;
        int kk = (ln & 3) * 2 + (r >> 1) * 8;
        int tap = ks >> 1, ci0 = (ks & 1) * 16;
        float w0 = w2[oc * 288 + (ci0 + kk) * 9 + tap];
        float w1v = w2[oc * 288 + (ci0 + kk + 1) * 9 + tap];
#pragma unroll
        for (int s = 0; s < 3; s++) {
            __nv_bfloat16 h0 = __float2bfloat16(w0);
            __nv_bfloat16 h1 = __float2bfloat16(w1v);
            w0 -= __bfloat162float(h0);
            w1v -= __bfloat162float(h1);
            sAf[((s * 4 + mt) * 18 + ks) * 128 + ln * 4 + r] =
                (uint32_t)*(uint16_t*)&h0 | ((uint32_t)*(uint16_t*)&h1 << 16);
        }
    }

    float biasr[4][2];
#pragma unroll
    for (int mt = 0; mt < 4; mt++) {
        biasr[mt][0] = b2[mt * 16 + (lane >> 2)];
        biasr[mt][1] = b2[mt * 16 + (lane >> 2) + 8];
    }

    // per-thread B position base offsets (elements) — n = lane>>2 per nt block
    int posoff[8];
#pragma unroll
    for (int nt = 0; nt < 8; nt++) {
        int pos = wid * 64 + nt * 8 + (lane >> 2);
        posoff[nt] = ((pos >> 4) * 18 + (pos & 15)) * 40;
    }

    for (int img = blockIdx.x; img < BATCH; img += gridDim.x) {
        // stage input channel-last with halo
        const float* in = g_c1 + img * 16384;
        for (int i = t; i < 4096; i += 256) {
            float4 v = ((const float4*)in)[i];
            int e = i * 4, ci = e >> 9, rem = e & 511, h = rem >> 4, w = rem & 15;
            __nv_bfloat16* p = sIn + ((h + 1) * 18 + (w + 1)) * 40 + ci;
            p[0]   = __float2bfloat16(v.x);
            p[40]  = __float2bfloat16(v.y);
            p[80]  = __float2bfloat16(v.z);
            p[120] = __float2bfloat16(v.w);
        }
        __syncthreads();

        float acc[4][8][4];
#pragma unroll
        for (int mt = 0; mt < 4; mt++)
#pragma unroll
            for (int nt = 0; nt < 8; nt++)
#pragma unroll
                for (int q = 0; q < 4; q++) acc[mt][nt][q] = 0.f;

#pragma unroll 2
        for (int ks = 0; ks < 18; ks++) {
            int tap = ks >> 1, ci0 = (ks & 1) * 16;
            int dy = tap / 3, dx = tap - dy * 3;
            int toff = (dy * 18 + dx) * 40 + ci0 + (lane & 3) * 2;

            uint32_t bfr[8][2];
#pragma unroll
            for (int nt = 0; nt < 8; nt++) {
                const __nv_bfloat16* bp = sIn + posoff[nt] + toff;
                bfr[nt][0] = *(const uint32_t*)bp;
                bfr[nt][1] = *(const uint32_t*)(bp + 8);
            }
#pragma unroll
            for (int s = 0; s < 3; s++)
#pragma unroll
                for (int mt = 0; mt < 4; mt++) {
                    uint4 av = ((const uint4*)(sAf + ((s * 4 + mt) * 18 + ks) * 128))[lane];
                    uint32_t a[4] = {av.x, av.y, av.z, av.w};
#pragma unroll
                    for (int nt = 0; nt < 8; nt++)
                        mma_bf16(acc[mt][nt], a, bfr[nt]);
                }
        }

        // epilogue: +bias, spike, in-thread 2x2 pool (D frag: ch=lane>>2, pos=(lane&3)*2)
        float* xout = g_xflat + img * 8192;
#pragma unroll
        for (int mt = 0; mt < 4; mt++)
#pragma unroll
            for (int rh = 0; rh < 2; rh++) {
                int ch = mt * 16 + (lane >> 2) + rh * 8;
                float bv = biasr[mt][rh];
#pragma unroll
                for (int np = 0; np < 4; np++) {
                    int nt = (np & 1) + (np >> 1) * 4;   // {0,1,4,5}
                    float s0 = (acc[mt][nt][rh * 2]         + bv > 1.f) ? 1.f : 0.f;
                    float s1 = (acc[mt][nt][rh * 2 + 1]     + bv > 1.f) ? 1.f : 0.f;
                    float s2 = (acc[mt][nt + 2][rh * 2]     + bv > 1.f) ? 1.f : 0.f;
                    float s3 = (acc[mt][nt + 2][rh * 2 + 1] + bv > 1.f) ? 1.f : 0.f;
                    int h = wid * 4 + (nt >> 1);
                    int ph = h >> 1;
                    int pw = (nt & 1) * 4 + (lane & 3);
                    xout[ch * 128 + ph * 8 + pw] = (s0 + s1 + s2 + s3) * 0.25f;
                }
            }
        __syncthreads();   // all warps done reading sIn before next stage
    }
}

// ---------------------------------------------------------------------------
// Kernel 3: fc1 GEMM (proven R1 version)
// ---------------------------------------------------------------------------
__global__ void __launch_bounds__(256) fc1_kernel(const float* __restrict__ W,
                                                  const float* __restrict__ bias) {
    __shared__ float sA[64][64];
    __shared__ float sW2[64][32];
    const int t = threadIdx.x;
    const int row0 = blockIdx.x * 64;
    const int n0 = blockIdx.y * 32;
    const int tx = t & 15, ty = t >> 4;

    const int lr = t >> 2, lk = (t & 3) * 16;
    const int wn = t >> 3, wk = (t & 7) * 8;

    float acc[4][2];
#pragma unroll
    for (int r = 0; r < 4; r++) { acc[r][0] = 0.f; acc[r][1] = 0.f; }

    for (int k0 = 0; k0 < 8192; k0 += 64) {
#pragma unroll
        for (int j = 0; j < 4; j++) {
            float4 v = *(const float4*)&g_xflat[(row0 + lr) * 8192 + k0 + lk + 4 * j];
            sA[lk + 4 * j + 0][lr] = v.x;
            sA[lk + 4 * j + 1][lr] = v.y;
            sA[lk + 4 * j + 2][lr] = v.z;
            sA[lk + 4 * j + 3][lr] = v.w;
        }
#pragma unroll
        for (int j = 0; j < 2; j++) {
            float4 v = *(const float4*)&W[(n0 + wn) * 8192 + k0 + wk + 4 * j];
            sW2[wk + 4 * j + 0][wn] = v.x;
            sW2[wk + 4 * j + 1][wn] = v.y;
            sW2[wk + 4 * j + 2][wn] = v.z;
            sW2[wk + 4 * j + 3][wn] = v.w;
        }
        __syncthreads();
#pragma unroll
        for (int k = 0; k < 64; k++) {
            float4 a = *(const float4*)&sA[k][ty * 4];
            float2 w = *(const float2*)&sW2[k][tx * 2];
            acc[0][0] += a.x * w.x; acc[0][1] += a.x * w.y;
            acc[1][0] += a.y * w.x; acc[1][1] += a.y * w.y;
            acc[2][0] += a.z * w.x; acc[2][1] += a.z * w.y;
            acc[3][0] += a.w * w.x; acc[3][1] += a.w * w.y;
        }
        __syncthreads();
    }
#pragma unroll
    for (int r = 0; r < 4; r++)
#pragma unroll
        for (int c = 0; c < 2; c++)
            g_cur3[(row0 + ty * 4 + r) * 256 + n0 + tx * 2 + c] =
                acc[r][c] + bias[n0 + tx * 2 + c];
}

// ---------------------------------------------------------------------------
// Kernel 4: 25-step LIF recurrence (proven R1 version)
// ---------------------------------------------------------------------------
#define REC_W2S (256 * 129)
#define REC_SMEM_BYTES ((REC_W2S + 1280 + 128 + 16 + 2048 + 1024) * 4)

__global__ void __launch_bounds__(256, 1) rec_kernel(const float* __restrict__ w2,
                                                     const float* __restrict__ b2,
                                                     const float* __restrict__ w3,
                                                     const float* __restrict__ b3,
                                                     float* __restrict__ out) {
    extern __shared__ float smr[];
    float* w2s   = smr;
    float* w3s   = w2s + REC_W2S;
    float* b2s   = w3s + 1280;
    float* b3s   = b2s + 128;
    float* spk3s = b3s + 16;
    float* spk4s = spk3s + 2048;

    const int t = threadIdx.x;
    const int rowbase = blockIdx.x * 8;

    for (int idx = t; idx < 128 * 256; idx += 256) {
        int j = idx >> 8, i = idx & 255;
        w2s[i * 129 + j] = w2[idx];
    }
    for (int idx = t; idx < 1280; idx += 256) {
        int j = idx >> 7, k = idx & 127;
        w3s[k * 10 + j] = w3[idx];
    }
    if (t < 128) b2s[t] = b2[t];
    if (t < 10)  b3s[t] = b3[t];
    __syncthreads();

    float mem3[8], c3[8];
#pragma unroll
    for (int r = 0; r < 8; r++) {
        mem3[r] = 0.f;
        c3[r] = g_cur3[(rowbase + r) * 256 + t];
    }
    const int j4 = t & 127, rg = t >> 7;
    float mem4[4] = {0.f, 0.f, 0.f, 0.f};
    const float b2v = b2s[j4];
    float mem5 = 0.f;
    const int r5 = t / 10, j5 = t % 10;
    const float b3v = (t < 80) ? b3s[j5] : 0.f;

    for (int step = 0; step < NSTEPS; step++) {
#pragma unroll
        for (int r = 0; r < 8; r++) {
            float reset = (mem3[r] > 1.f) ? 1.f : 0.f;
            float m = 0.95f * mem3[r] + c3[r] - reset;
            mem3[r] = m;
            spk3s[t * 8 + r] = (m > 1.f) ? 1.f : 0.f;
        }
        __syncthreads();

        float a4[4];
#pragma unroll
        for (int r = 0; r < 4; r++) a4[r] = b2v;
#pragma unroll 4
        for (int i = 0; i < 256; i++) {
            float w = w2s[i * 129 + j4];
            float4 s = *(const float4*)&spk3s[i * 8 + rg * 4];
            a4[0] += w * s.x; a4[1] += w * s.y; a4[2] += w * s.z; a4[3] += w * s.w;
        }
#pragma unroll
        for (int r = 0; r < 4; r++) {
            float reset = (mem4[r] > 1.f) ? 1.f : 0.f;
            float m = 0.95f * mem4[r] + a4[r] - reset;
            mem4[r] = m;
            spk4s[j4 * 8 + rg * 4 + r] = (m > 1.f) ? 1.f : 0.f;
        }
        __syncthreads();

        if (t < 80) {
            float a5 = b3v;
#pragma unroll 8
            for (int k = 0; k < 128; k++)
                a5 += w3s[k * 10 + j5] * spk4s[k * 8 + r5];
            float reset = (mem5 > 1.f) ? 1.f : 0.f;
            float m = 0.95f * mem5 + a5 - reset;
            mem5 = m;
            out[(step * 1024 + rowbase + r5) * 10 + j5] = (m > 1.f) ? 1.f : 0.f;
        }
        __syncthreads();
    }
}

// ---------------------------------------------------------------------------
extern "C" void kernel_launch(void* const* d_in, const int* in_sizes, int n_in,
                              void* d_out, int out_size) {
    const float* x       = (const float*)d_in[0];
    const float* conv1_w = (const float*)d_in[1];
    const float* conv1_b = (const float*)d_in[2];
    const float* conv2_w = (const float*)d_in[3];
    const float* conv2_b = (const float*)d_in[4];
    const float* fc1_w   = (const float*)d_in[5];
    const float* fc1_b   = (const float*)d_in[6];
    const float* fc2_w   = (const float*)d_in[7];
    const float* fc2_b   = (const float*)d_in[8];
    const float* fc3_w   = (const float*)d_in[9];
    const float* fc3_b   = (const float*)d_in[10];
    float* out = (float*)d_out;

    cudaFuncSetAttribute(conv2_mma, cudaFuncAttributeMaxDynamicSharedMemorySize,
                         C2_SMEM);
    cudaFuncSetAttribute(rec_kernel, cudaFuncAttributeMaxDynamicSharedMemorySize,
                         REC_SMEM_BYTES);

    conv1_kernel<<<BATCH, 256>>>(x, conv1_w, conv1_b);
    conv2_mma<<<148, 256, C2_SMEM>>>(conv2_w, conv2_b);
    fc1_kernel<<<dim3(16, 8), 256>>>(fc1_w, fc1_b);
    rec_kernel<<<128, 256, REC_SMEM_BYTES>>>(fc2_w, fc2_b, fc3_w, fc3_b, out);
}

// round 6
// speedup vs baseline: 2.5502x; 1.6988x over previous
#include <cuda_runtime.h>
#include <cuda_fp16.h>
#include <cstdint>

#define BATCH 1024
#define NSTEPS 25

// scratch (device globals)
__device__ float  g_c1[BATCH * 32 * 32 * 16];     // pooled spikes after conv1
__device__ __half g_xh[BATCH * 8192];             // pooled spikes after conv2 (fp16, exact)
__device__ __half g_wh0[256 * 8192];              // fc1_w hi split
__device__ __half g_wh1[256 * 8192];              // fc1_w lo split
__device__ float  g_part[2 * 1024 * 256];         // fc1 K-split partials

// ---------------------------------------------------------------------------
// mma.sync m16n8k16 fp16 (baseline PTX)
// ---------------------------------------------------------------------------
__device__ __forceinline__ void mma_f16(float* d, const uint32_t* a, const uint32_t* b) {
    asm volatile(
        "mma.sync.aligned.m16n8k16.row.col.f32.f16.f16.f32 "
        "{%0,%1,%2,%3}, {%4,%5,%6,%7}, {%8,%9}, {%0,%1,%2,%3};"
        : "+f"(d[0]), "+f"(d[1]), "+f"(d[2]), "+f"(d[3])
        : "r"(a[0]), "r"(a[1]), "r"(a[2]), "r"(a[3]), "r"(b[0]), "r"(b[1]));
}

// ---------------------------------------------------------------------------
// Kernel 1: conv1 (1->32, 3x3 SAME) + spike + pool  (proven R1 version)
// ---------------------------------------------------------------------------
__global__ void __launch_bounds__(256) conv1_kernel(const float* __restrict__ x,
                                                    const float* __restrict__ w1,
                                                    const float* __restrict__ b1) {
    __shared__ float sIn[66 * 34];
    __shared__ float sW[32 * 9];
    __shared__ float sB[32];
    const int t = threadIdx.x;
    const int img = blockIdx.x;

    for (int i = t; i < 66 * 34; i += 256) sIn[i] = 0.f;
    for (int i = t; i < 288; i += 256) sW[i] = w1[i];
    if (t < 32) sB[t] = b1[t];
    __syncthreads();

    const float* xi = x + img * 2048;
    for (int i = t; i < 2048; i += 256) {
        int y = i >> 5, xc = i & 31;
        sIn[(y + 1) * 34 + (xc + 1)] = xi[i];
    }
    __syncthreads();

    for (int cellBase = 0; cellBase < 512; cellBase += 256) {
        int cell = cellBase + t;
        int ph = cell >> 4, pw = cell & 15;
        float in[4][4];
#pragma unroll
        for (int r = 0; r < 4; r++)
#pragma unroll
            for (int c = 0; c < 4; c++)
                in[r][c] = sIn[(2 * ph + r) * 34 + (2 * pw + c)];

        for (int ch = 0; ch < 32; ch++) {
            float wv[9];
#pragma unroll
            for (int k = 0; k < 9; k++) wv[k] = sW[ch * 9 + k];
            float bb = sB[ch];
            float cnt = 0.f;
#pragma unroll
            for (int dy = 0; dy < 2; dy++)
#pragma unroll
                for (int dx = 0; dx < 2; dx++) {
                    float s = bb;
#pragma unroll
                    for (int ky = 0; ky < 3; ky++)
#pragma unroll
                        for (int kx = 0; kx < 3; kx++)
                            s += wv[ky * 3 + kx] * in[dy + ky][dx + kx];
                    cnt += (s > 1.f) ? 1.f : 0.f;
                }
            g_c1[((img * 32 + ch) * 32 + ph) * 16 + pw] = cnt * 0.25f;
        }
    }
}

// ---------------------------------------------------------------------------
// Kernel 2: conv2 via mma.sync fp16 2-split, channel-last staged input,
//   direct per-lane B loads. Output written as fp16 (exact quarters).
// ---------------------------------------------------------------------------
#define C2_AF_BYTES 73728                     // 2*4*18*128 u32
#define C2_IN_BYTES 48960                     // 34*18*40 fp16
#define C2_SMEM (C2_AF_BYTES + C2_IN_BYTES + 256)

__global__ void __launch_bounds__(256, 1) conv2_mma(const float* __restrict__ w2,
                                                    const float* __restrict__ b2) {
    extern __shared__ char sm[];
    uint32_t* sAf = (uint32_t*)sm;
    __half* sIn = (__half*)(sm + C2_AF_BYTES);

    const int t = threadIdx.x;
    const int lane = t & 31, wid = t >> 5;

    for (int i = t; i < C2_IN_BYTES / 4; i += 256) ((uint32_t*)sIn)[i] = 0u;

    // weight fragments, 2 fp16 splits, K order (tap, ci)
    for (int idx = t; idx < 4 * 18 * 32 * 4; idx += 256) {
        int r = idx & 3, ln = (idx >> 2) & 31, ks = (idx >> 7) % 18, mt = idx / (128 * 18);
        int oc = mt * 16 + (ln >> 2) + (r & 1) * 8;
        int kk = (ln & 3) * 2 + (r >> 1) * 8;
        int tap = ks >> 1, ci0 = (ks & 1) * 16;
        float w0 = w2[oc * 288 + (ci0 + kk) * 9 + tap];
        float w1v = w2[oc * 288 + (ci0 + kk + 1) * 9 + tap];
#pragma unroll
        for (int s = 0; s < 2; s++) {
            __half h0 = __float2half(w0);
            __half h1 = __float2half(w1v);
            w0 -= __half2float(h0);
            w1v -= __half2float(h1);
            sAf[((s * 4 + mt) * 18 + ks) * 128 + ln * 4 + r] =
                (uint32_t)*(uint16_t*)&h0 | ((uint32_t)*(uint16_t*)&h1 << 16);
        }
    }

    float biasr[4][2];
#pragma unroll
    for (int mt = 0; mt < 4; mt++) {
        biasr[mt][0] = b2[mt * 16 + (lane >> 2)];
        biasr[mt][1] = b2[mt * 16 + (lane >> 2) + 8];
    }

    int posoff[8];
#pragma unroll
    for (int nt = 0; nt < 8; nt++) {
        int pos = wid * 64 + nt * 8 + (lane >> 2);
        posoff[nt] = ((pos >> 4) * 18 + (pos & 15)) * 40;
    }

    for (int img = blockIdx.x; img < BATCH; img += gridDim.x) {
        const float* in = g_c1 + img * 16384;
        for (int i = t; i < 4096; i += 256) {
            float4 v = ((const float4*)in)[i];
            int e = i * 4, ci = e >> 9, rem = e & 511, h = rem >> 4, w = rem & 15;
            __half* p = sIn + ((h + 1) * 18 + (w + 1)) * 40 + ci;
            p[0]   = __float2half(v.x);
            p[40]  = __float2half(v.y);
            p[80]  = __float2half(v.z);
            p[120] = __float2half(v.w);
        }
        __syncthreads();

        float acc[4][8][4];
#pragma unroll
        for (int mt = 0; mt < 4; mt++)
#pragma unroll
            for (int nt = 0; nt < 8; nt++)
#pragma unroll
                for (int q = 0; q < 4; q++) acc[mt][nt][q] = 0.f;

#pragma unroll 2
        for (int ks = 0; ks < 18; ks++) {
            int tap = ks >> 1, ci0 = (ks & 1) * 16;
            int dy = tap / 3, dx = tap - dy * 3;
            int toff = (dy * 18 + dx) * 40 + ci0 + (lane & 3) * 2;

            uint32_t bfr[8][2];
#pragma unroll
            for (int nt = 0; nt < 8; nt++) {
                const __half* bp = sIn + posoff[nt] + toff;
                bfr[nt][0] = *(const uint32_t*)bp;
                bfr[nt][1] = *(const uint32_t*)(bp + 8);
            }
#pragma unroll
            for (int s = 0; s < 2; s++)
#pragma unroll
                for (int mt = 0; mt < 4; mt++) {
                    uint4 av = ((const uint4*)(sAf + ((s * 4 + mt) * 18 + ks) * 128))[lane];
                    uint32_t a[4] = {av.x, av.y, av.z, av.w};
#pragma unroll
                    for (int nt = 0; nt < 8; nt++)
                        mma_f16(acc[mt][nt], a, bfr[nt]);
                }
        }

        __half* xout = g_xh + img * 8192;
#pragma unroll
        for (int mt = 0; mt < 4; mt++)
#pragma unroll
            for (int rh = 0; rh < 2; rh++) {
                int ch = mt * 16 + (lane >> 2) + rh * 8;
                float bv = biasr[mt][rh];
#pragma unroll
                for (int np = 0; np < 4; np++) {
                    int nt = (np & 1) + (np >> 1) * 4;   // {0,1,4,5}
                    float s0 = (acc[mt][nt][rh * 2]         + bv > 1.f) ? 1.f : 0.f;
                    float s1 = (acc[mt][nt][rh * 2 + 1]     + bv > 1.f) ? 1.f : 0.f;
                    float s2 = (acc[mt][nt + 2][rh * 2]     + bv > 1.f) ? 1.f : 0.f;
                    float s3 = (acc[mt][nt + 2][rh * 2 + 1] + bv > 1.f) ? 1.f : 0.f;
                    int h = wid * 4 + (nt >> 1);
                    int ph = h >> 1;
                    int pw = (nt & 1) * 4 + (lane & 3);
                    xout[ch * 128 + ph * 8 + pw] = __float2half((s0 + s1 + s2 + s3) * 0.25f);
                }
            }
        __syncthreads();
    }
}

// ---------------------------------------------------------------------------
// Kernel 3a: split fc1_w into 2 fp16 planes
// ---------------------------------------------------------------------------
__global__ void __launch_bounds__(256) wprep_kernel(const float* __restrict__ W) {
    int i = blockIdx.x * 256 + threadIdx.x;
    if (i < 256 * 8192) {
        float w = W[i];
        __half h0 = __float2half(w);
        float r = w - __half2float(h0);
        g_wh0[i] = h0;
        g_wh1[i] = __float2half(r);
    }
}

// ---------------------------------------------------------------------------
// Kernel 3b: fc1 via mma.sync fp16 2-split, split-K=2, fp32 partials.
//   grid (16 rowtiles x 4 coltiles x 2 ksplits), 256 thr; tile 64x64, K=4096.
//   warps 2(M)x4(N): warp tile 32x16.
// ---------------------------------------------------------------------------
__global__ void __launch_bounds__(256) fc1_mma() {
    __shared__ uint32_t sXu[64 * 36];        // [row][72 fp16]
    __shared__ uint32_t sWu[2][64 * 36];     // [split][n][72 fp16]

    const int t = threadIdx.x;
    const int lane = t & 31, wid = t >> 5;
    const int wm = wid & 1, wn = wid >> 1;
    const int rowbase = blockIdx.x * 64;
    const int n0 = blockIdx.y * 64;
    const int k0 = blockIdx.z * 4096;

    const int lrow = t >> 2, lk16 = (t & 3) * 16;   // loader: row/n, k offset
    const int lk8 = (t & 3) * 8;                    // u32 offset in smem row

    float acc[2][2][4];
#pragma unroll
    for (int mt = 0; mt < 2; mt++)
#pragma unroll
        for (int nt = 0; nt < 2; nt++)
#pragma unroll
            for (int q = 0; q < 4; q++) acc[mt][nt][q] = 0.f;

    for (int kc = 0; kc < 64; kc++) {
        const int kbase = k0 + kc * 64;
        // prefetch gmem
        const uint4* xp = (const uint4*)(g_xh + (rowbase + lrow) * 8192 + kbase + lk16);
        uint4 x0 = xp[0], x1 = xp[1];
        const uint4* w0p = (const uint4*)(g_wh0 + (n0 + lrow) * 8192 + kbase + lk16);
        uint4 wa0 = w0p[0], wa1 = w0p[1];
        const uint4* w1p = (const uint4*)(g_wh1 + (n0 + lrow) * 8192 + kbase + lk16);
        uint4 wb0 = w1p[0], wb1 = w1p[1];

        __syncthreads();   // previous chunk consumed
        uint32_t* xd = sXu + lrow * 36 + lk8;
        xd[0] = x0.x; xd[1] = x0.y; xd[2] = x0.z; xd[3] = x0.w;
        xd[4] = x1.x; xd[5] = x1.y; xd[6] = x1.z; xd[7] = x1.w;
        uint32_t* wd0 = sWu[0] + lrow * 36 + lk8;
        wd0[0] = wa0.x; wd0[1] = wa0.y; wd0[2] = wa0.z; wd0[3] = wa0.w;
        wd0[4] = wa1.x; wd0[5] = wa1.y; wd0[6] = wa1.z; wd0[7] = wa1.w;
        uint32_t* wd1 = sWu[1] + lrow * 36 + lk8;
        wd1[0] = wb0.x; wd1[1] = wb0.y; wd1[2] = wb0.z; wd1[3] = wb0.w;
        wd1[4] = wb1.x; wd1[5] = wb1.y; wd1[6] = wb1.z; wd1[7] = wb1.w;
        __syncthreads();

#pragma unroll
        for (int ks = 0; ks < 4; ks++) {
            const int kw = ks * 8 + (lane & 3);
            uint32_t a[2][4];
#pragma unroll
            for (int mt = 0; mt < 2; mt++) {
                int row = wm * 32 + mt * 16 + (lane >> 2);
                a[mt][0] = sXu[row * 36 + kw];
                a[mt][1] = sXu[(row + 8) * 36 + kw];
                a[mt][2] = sXu[row * 36 + kw + 4];
                a[mt][3] = sXu[(row + 8) * 36 + kw + 4];
            }
#pragma unroll
            for (int s = 0; s < 2; s++)
#pragma unroll
                for (int nt = 0; nt < 2; nt++) {
                    int n = wn * 16 + nt * 8 + (lane >> 2);
                    uint32_t b[2];
                    b[0] = sWu[s][n * 36 + kw];
                    b[1] = sWu[s][n * 36 + kw + 4];
#pragma unroll
                    for (int mt = 0; mt < 2; mt++)
                        mma_f16(acc[mt][nt], a[mt], b);
                }
        }
    }

    float* outp = g_part + blockIdx.z * (1024 * 256);
    const int r0 = rowbase + wm * 32 + (lane >> 2);
    const int c0 = n0 + wn * 16 + (lane & 3) * 2;
#pragma unroll
    for (int mt = 0; mt < 2; mt++)
#pragma unroll
        for (int nt = 0; nt < 2; nt++) {
            int r = r0 + mt * 16, c = c0 + nt * 8;
            outp[r * 256 + c]           = acc[mt][nt][0];
            outp[r * 256 + c + 1]       = acc[mt][nt][1];
            outp[(r + 8) * 256 + c]     = acc[mt][nt][2];
            outp[(r + 8) * 256 + c + 1] = acc[mt][nt][3];
        }
}

// ---------------------------------------------------------------------------
// Kernel 4: 25-step LIF recurrence, 512 threads, split-K layer-4 GEMV.
//   Combines fc1 partials + bias into cur3 at load.
// ---------------------------------------------------------------------------
#define REC_W2S (256 * 129)
#define REC_SMEM_BYTES ((REC_W2S + 1280 + 128 + 16 + 256 + 2048 + 1024 + 2048) * 4)

__global__ void __launch_bounds__(512, 1) rec_kernel(const float* __restrict__ w2,
                                                     const float* __restrict__ b2,
                                                     const float* __restrict__ w3,
                                                     const float* __restrict__ b3,
                                                     const float* __restrict__ b1,
                                                     float* __restrict__ out) {
    extern __shared__ float smr[];
    float* w2s    = smr;                  // [i*129 + j]
    float* w3s    = w2s + REC_W2S;        // [k*10 + j]
    float* b2s    = w3s + 1280;
    float* b3s    = b2s + 128;
    float* b1s    = b3s + 16;             // [256]
    float* spk3s  = b1s + 256;            // [256][8]
    float* spk4s  = spk3s + 2048;         // [128][8]
    float* part44 = spk4s + 1024;         // [kh][j4][rg][4] = 2048

    const int t = threadIdx.x;
    const int rowbase = blockIdx.x * 8;

    for (int idx = t; idx < 128 * 256; idx += 512) {
        int j = idx >> 8, i = idx & 255;
        w2s[i * 129 + j] = w2[idx];
    }
    for (int idx = t; idx < 1280; idx += 512) {
        int j = idx >> 7, k = idx & 127;
        w3s[k * 10 + j] = w3[idx];
    }
    if (t < 128) b2s[t] = b2[t];
    if (t < 10)  b3s[t] = b3[t];
    if (t < 256) b1s[t] = b1[t];
    __syncthreads();

    // layer-3: thread owns neuron n3 for 4 rows (rh selects row half)
    const int n3 = t & 255, rh = t >> 8;
    float mem3[4], c3[4];
#pragma unroll
    for (int r = 0; r < 4; r++) {
        int row = rowbase + rh * 4 + r;
        mem3[r] = 0.f;
        c3[r] = (g_part[row * 256 + n3] + g_part[1024 * 256 + row * 256 + n3]) + b1s[n3];
    }
    // layer-4: j4, row group rg, K half kh
    const int j4 = t & 127, rg = (t >> 7) & 1, kh = t >> 8;
    float mem4[4] = {0.f, 0.f, 0.f, 0.f};
    const float b2v = b2s[j4];
    // layer-5
    float mem5 = 0.f;
    const int r5 = t / 10, j5 = t % 10;
    const float b3v = (t < 80) ? b3s[j5] : 0.f;

    for (int step = 0; step < NSTEPS; step++) {
        // layer 3 LIF (512 threads x 4 rows)
        float sp[4];
#pragma unroll
        for (int r = 0; r < 4; r++) {
            float reset = (mem3[r] > 1.f) ? 1.f : 0.f;
            float m = 0.95f * mem3[r] + c3[r] - reset;
            mem3[r] = m;
            sp[r] = (m > 1.f) ? 1.f : 0.f;
        }
        *(float4*)&spk3s[n3 * 8 + rh * 4] = make_float4(sp[0], sp[1], sp[2], sp[3]);
        __syncthreads();

        // layer 4 partial GEMV: half the K range per thread
        float a4[4] = {0.f, 0.f, 0.f, 0.f};
        const int i0 = kh * 128;
#pragma unroll 4
        for (int i = i0; i < i0 + 128; i++) {
            float w = w2s[i * 129 + j4];
            float4 s = *(const float4*)&spk3s[i * 8 + rg * 4];
            a4[0] += w * s.x; a4[1] += w * s.y; a4[2] += w * s.z; a4[3] += w * s.w;
        }
        *(float4*)&part44[((kh * 128 + j4) * 2 + rg) * 4] = make_float4(a4[0], a4[1], a4[2], a4[3]);
        __syncthreads();

        // layer 4 combine + LIF (first 256 threads)
        if (t < 256) {
            const int cj = t & 127, crg = t >> 7;
            float4 p0 = *(const float4*)&part44[(cj * 2 + crg) * 4];
            float4 p1 = *(const float4*)&part44[((128 + cj) * 2 + crg) * 4];
            float cur[4] = {p0.x + p1.x + b2v, p0.y + p1.y + b2v,
                            p0.z + p1.z + b2v, p0.w + p1.w + b2v};
            float s4[4];
#pragma unroll
            for (int r = 0; r < 4; r++) {
                float reset = (mem4[r] > 1.f) ? 1.f : 0.f;
                float m = 0.95f * mem4[r] + cur[r] - reset;
                mem4[r] = m;
                s4[r] = (m > 1.f) ? 1.f : 0.f;
            }
            *(float4*)&spk4s[cj * 8 + crg * 4] = make_float4(s4[0], s4[1], s4[2], s4[3]);
        }
        __syncthreads();

        // layer 5
        if (t < 80) {
            float a5 = b3v;
#pragma unroll 8
            for (int k = 0; k < 128; k++)
                a5 += w3s[k * 10 + j5] * spk4s[k * 8 + r5];
            float reset = (mem5 > 1.f) ? 1.f : 0.f;
            float m = 0.95f * mem5 + a5 - reset;
            mem5 = m;
            out[(step * 1024 + rowbase + r5) * 10 + j5] = (m > 1.f) ? 1.f : 0.f;
        }
        __syncthreads();
    }
}

// ---------------------------------------------------------------------------
extern "C" void kernel_launch(void* const* d_in, const int* in_sizes, int n_in,
                              void* d_out, int out_size) {
    const float* x       = (const float*)d_in[0];
    const float* conv1_w = (const float*)d_in[1];
    const float* conv1_b = (const float*)d_in[2];
    const float* conv2_w = (const float*)d_in[3];
    const float* conv2_b = (const float*)d_in[4];
    const float* fc1_w   = (const float*)d_in[5];
    const float* fc1_b   = (const float*)d_in[6];
    const float* fc2_w   = (const float*)d_in[7];
    const float* fc2_b   = (const float*)d_in[8];
    const float* fc3_w   = (const float*)d_in[9];
    const float* fc3_b   = (const float*)d_in[10];
    float* out = (float*)d_out;

    cudaFuncSetAttribute(conv2_mma, cudaFuncAttributeMaxDynamicSharedMemorySize,
                         C2_SMEM);
    cudaFuncSetAttribute(rec_kernel, cudaFuncAttributeMaxDynamicSharedMemorySize,
                         REC_SMEM_BYTES);

    conv1_kernel<<<BATCH, 256>>>(x, conv1_w, conv1_b);
    wprep_kernel<<<8192, 256>>>(fc1_w);
    conv2_mma<<<148, 256, C2_SMEM>>>(conv2_w, conv2_b);
    fc1_mma<<<dim3(16, 4, 2), 256>>>();
    rec_kernel<<<128, 512, REC_SMEM_BYTES>>>(fc2_w, fc2_b, fc3_w, fc3_b, fc1_b, out);
}

// round 7
// speedup vs baseline: 2.6249x; 1.0293x over previous
#include <cuda_runtime.h>
#include <cuda_fp16.h>
#include <cstdint>

#define BATCH 1024
#define NSTEPS 25

// scratch (device globals)
__device__ float  g_c1[BATCH * 32 * 32 * 16];     // pooled spikes after conv1
__device__ __half g_xh[BATCH * 8192];             // pooled spikes after conv2 (fp16, exact)
__device__ float  g_part[4 * 1024 * 256];         // fc1 K-split partials

// ---------------------------------------------------------------------------
// mma.sync m16n8k16 fp16 (baseline PTX)
// ---------------------------------------------------------------------------
__device__ __forceinline__ void mma_f16(float* d, const uint32_t* a, const uint32_t* b) {
    asm volatile(
        "mma.sync.aligned.m16n8k16.row.col.f32.f16.f16.f32 "
        "{%0,%1,%2,%3}, {%4,%5,%6,%7}, {%8,%9}, {%0,%1,%2,%3};"
        : "+f"(d[0]), "+f"(d[1]), "+f"(d[2]), "+f"(d[3])
        : "r"(a[0]), "r"(a[1]), "r"(a[2]), "r"(a[3]), "r"(b[0]), "r"(b[1]));
}
__device__ __forceinline__ uint32_t packh(__half a, __half b) {
    return (uint32_t)__half_as_ushort(a) | ((uint32_t)__half_as_ushort(b) << 16);
}

// ---------------------------------------------------------------------------
// Kernel 1: conv1 (1->32, 3x3 SAME) + spike + pool  (proven R1 version)
// ---------------------------------------------------------------------------
__global__ void __launch_bounds__(256) conv1_kernel(const float* __restrict__ x,
                                                    const float* __restrict__ w1,
                                                    const float* __restrict__ b1) {
    __shared__ float sIn[66 * 34];
    __shared__ float sW[32 * 9];
    __shared__ float sB[32];
    const int t = threadIdx.x;
    const int img = blockIdx.x;

    for (int i = t; i < 66 * 34; i += 256) sIn[i] = 0.f;
    for (int i = t; i < 288; i += 256) sW[i] = w1[i];
    if (t < 32) sB[t] = b1[t];
    __syncthreads();

    const float* xi = x + img * 2048;
    for (int i = t; i < 2048; i += 256) {
        int y = i >> 5, xc = i & 31;
        sIn[(y + 1) * 34 + (xc + 1)] = xi[i];
    }
    __syncthreads();

    for (int cellBase = 0; cellBase < 512; cellBase += 256) {
        int cell = cellBase + t;
        int ph = cell >> 4, pw = cell & 15;
        float in[4][4];
#pragma unroll
        for (int r = 0; r < 4; r++)
#pragma unroll
            for (int c = 0; c < 4; c++)
                in[r][c] = sIn[(2 * ph + r) * 34 + (2 * pw + c)];

        for (int ch = 0; ch < 32; ch++) {
            float wv[9];
#pragma unroll
            for (int k = 0; k < 9; k++) wv[k] = sW[ch * 9 + k];
            float bb = sB[ch];
            float cnt = 0.f;
#pragma unroll
            for (int dy = 0; dy < 2; dy++)
#pragma unroll
                for (int dx = 0; dx < 2; dx++) {
                    float s = bb;
#pragma unroll
                    for (int ky = 0; ky < 3; ky++)
#pragma unroll
                        for (int kx = 0; kx < 3; kx++)
                            s += wv[ky * 3 + kx] * in[dy + ky][dx + kx];
                    cnt += (s > 1.f) ? 1.f : 0.f;
                }
            g_c1[((img * 32 + ch) * 32 + ph) * 16 + pw] = cnt * 0.25f;
        }
    }
}

// ---------------------------------------------------------------------------
// Kernel 2: conv2 via mma.sync fp16 2-split.
//   Channel-interleaved staged input ([0,1,8,9,2,3,10,11,...] per 16-chunk,
//   stride 48 halves): B fragment = one LDS.64, conflict-free.
// ---------------------------------------------------------------------------
#define C2_AF_BYTES 73728                     // 2*4*18*128 u32
#define C2_IN_BYTES (34 * 18 * 48 * 2)        // 58752
#define C2_SMEM (C2_AF_BYTES + C2_IN_BYTES + 256)

__global__ void __launch_bounds__(256, 1) conv2_mma(const float* __restrict__ w2,
                                                    const float* __restrict__ b2) {
    extern __shared__ char sm[];
    uint32_t* sAf = (uint32_t*)sm;
    __half* sIn = (__half*)(sm + C2_AF_BYTES);

    const int t = threadIdx.x;
    const int lane = t & 31, wid = t >> 5;

    for (int i = t; i < C2_IN_BYTES / 4; i += 256) ((uint32_t*)sIn)[i] = 0u;

    // weight fragments, 2 fp16 splits, K order (tap, ci)
    for (int idx = t; idx < 4 * 18 * 32 * 4; idx += 256) {
        int r = idx & 3, ln = (idx >> 2) & 31, ks = (idx >> 7) % 18, mt = idx / (128 * 18);
        int oc = mt * 16 + (ln >> 2) + (r & 1) * 8;
        int kk = (ln & 3) * 2 + (r >> 1) * 8;
        int tap = ks >> 1, ci0 = (ks & 1) * 16;
        float w0 = w2[oc * 288 + (ci0 + kk) * 9 + tap];
        float w1v = w2[oc * 288 + (ci0 + kk + 1) * 9 + tap];
#pragma unroll
        for (int s = 0; s < 2; s++) {
            __half h0 = __float2half(w0);
            __half h1 = __float2half(w1v);
            w0 -= __half2float(h0);
            w1v -= __half2float(h1);
            sAf[((s * 4 + mt) * 18 + ks) * 128 + ln * 4 + r] = packh(h0, h1);
        }
    }

    float biasr[4][2];
#pragma unroll
    for (int mt = 0; mt < 4; mt++) {
        biasr[mt][0] = b2[mt * 16 + (lane >> 2)];
        biasr[mt][1] = b2[mt * 16 + (lane >> 2) + 8];
    }

    int posoff[8];
#pragma unroll
    for (int nt = 0; nt < 8; nt++) {
        int pos = wid * 64 + nt * 8 + (lane >> 2);
        posoff[nt] = ((pos >> 4) * 18 + (pos & 15)) * 48;
    }

    for (int img = blockIdx.x; img < BATCH; img += gridDim.x) {
        // stage input channel-interleaved with halo
        const float* in = g_c1 + img * 16384;
        for (int i = t; i < 4096; i += 256) {
            float4 v = ((const float4*)in)[i];
            int e = i * 4, ci = e >> 9, rem = e & 511, h = rem >> 4, w = rem & 15;
            int np = (ci & 16) + ((ci & 6) << 1) + (ci & 1) + (((ci >> 3) & 1) << 1);
            __half* p = sIn + ((h + 1) * 18 + (w + 1)) * 48 + np;
            p[0]   = __float2half(v.x);
            p[48]  = __float2half(v.y);
            p[96]  = __float2half(v.z);
            p[144] = __float2half(v.w);
        }
        __syncthreads();

        float acc[4][8][4];
#pragma unroll
        for (int mt = 0; mt < 4; mt++)
#pragma unroll
            for (int nt = 0; nt < 8; nt++)
#pragma unroll
                for (int q = 0; q < 4; q++) acc[mt][nt][q] = 0.f;

#pragma unroll 2
        for (int ks = 0; ks < 18; ks++) {
            int tap = ks >> 1, ci0 = (ks & 1) * 16;
            int dy = tap / 3, dx = tap - dy * 3;
            int toff = (dy * 18 + dx) * 48 + ci0 + (lane & 3) * 4;

            uint32_t bfr[8][2];
#pragma unroll
            for (int nt = 0; nt < 8; nt++) {
                uint2 bv = *(const uint2*)(sIn + posoff[nt] + toff);
                bfr[nt][0] = bv.x; bfr[nt][1] = bv.y;
            }
#pragma unroll
            for (int s = 0; s < 2; s++)
#pragma unroll
                for (int mt = 0; mt < 4; mt++) {
                    uint4 av = ((const uint4*)(sAf + ((s * 4 + mt) * 18 + ks) * 128))[lane];
                    uint32_t a[4] = {av.x, av.y, av.z, av.w};
#pragma unroll
                    for (int nt = 0; nt < 8; nt++)
                        mma_f16(acc[mt][nt], a, bfr[nt]);
                }
        }

        __half* xout = g_xh + img * 8192;
#pragma unroll
        for (int mt = 0; mt < 4; mt++)
#pragma unroll
            for (int rh = 0; rh < 2; rh++) {
                int ch = mt * 16 + (lane >> 2) + rh * 8;
                float bv = biasr[mt][rh];
#pragma unroll
                for (int np2 = 0; np2 < 4; np2++) {
                    int nt = (np2 & 1) + (np2 >> 1) * 4;   // {0,1,4,5}
                    float s0 = (acc[mt][nt][rh * 2]         + bv > 1.f) ? 1.f : 0.f;
                    float s1 = (acc[mt][nt][rh * 2 + 1]     + bv > 1.f) ? 1.f : 0.f;
                    float s2 = (acc[mt][nt + 2][rh * 2]     + bv > 1.f) ? 1.f : 0.f;
                    float s3 = (acc[mt][nt + 2][rh * 2 + 1] + bv > 1.f) ? 1.f : 0.f;
                    int h = wid * 4 + (nt >> 1);
                    int ph = h >> 1;
                    int pw = (nt & 1) * 4 + (lane & 3);
                    xout[ch * 128 + ph * 8 + pw] = __float2half((s0 + s1 + s2 + s3) * 0.25f);
                }
            }
        __syncthreads();
    }
}

// ---------------------------------------------------------------------------
// Kernel 3: fc1 via mma.sync fp16 2-split (split happens at stage time from
//   fp32 W — no prep kernel). Split-K=4, double-buffered smem, one sync/iter.
//   grid (16, 4, 4) = 256 CTAs; tile 64 rows x 64 cols x K=2048.
// ---------------------------------------------------------------------------
#define FC1_SMEM ((2 * 2304 + 4 * 2304) * 4)   // 55296 B

__global__ void __launch_bounds__(256) fc1_mma(const float* __restrict__ W) {
    extern __shared__ uint32_t smf[];
    uint32_t* sX = smf;                    // [buf][64*36]
    uint32_t* sW2 = smf + 2 * 2304;        // [buf][split][64*36]

    const int t = threadIdx.x;
    const int lane = t & 31, wid = t >> 5;
    const int wm = wid & 1, wn = wid >> 1;
    const int rowbase = blockIdx.x * 64;
    const int n0 = blockIdx.y * 64;
    const int k0 = blockIdx.z * 2048;

    const int lrow = t >> 2, lk16 = (t & 3) * 16, lk8 = (t & 3) * 8;

    const uint4* xsrc = (const uint4*)(g_xh + (rowbase + lrow) * 8192 + k0 + lk16);
    const float4* wsrc = (const float4*)(W + (n0 + lrow) * 8192 + k0 + lk16);

    float acc[2][2][4];
#pragma unroll
    for (int mt = 0; mt < 2; mt++)
#pragma unroll
        for (int nt = 0; nt < 2; nt++)
#pragma unroll
            for (int q = 0; q < 4; q++) acc[mt][nt][q] = 0.f;

    uint4 xr0, xr1;
    float4 wr[4];

    xr0 = xsrc[0]; xr1 = xsrc[1];
#pragma unroll
    for (int j = 0; j < 4; j++) wr[j] = wsrc[j];

    // store prologue into buf 0
    {
        uint32_t* xd = sX + lrow * 36 + lk8;
        xd[0] = xr0.x; xd[1] = xr0.y; xd[2] = xr0.z; xd[3] = xr0.w;
        xd[4] = xr1.x; xd[5] = xr1.y; xd[6] = xr1.z; xd[7] = xr1.w;
        const float* wf = (const float*)wr;
        uint32_t* w0d = sW2 + lrow * 36 + lk8;
        uint32_t* w1d = sW2 + 2304 + lrow * 36 + lk8;
#pragma unroll
        for (int j = 0; j < 8; j++) {
            float a = wf[2 * j], b = wf[2 * j + 1];
            __half ha = __float2half(a), hb = __float2half(b);
            w0d[j] = packh(ha, hb);
            w1d[j] = packh(__float2half(a - __half2float(ha)),
                           __float2half(b - __half2float(hb)));
        }
    }

    for (int kc = 0; kc < 32; kc++) {
        const int cb = kc & 1;
        if (kc < 31) {
            xr0 = xsrc[(kc + 1) * 8]; xr1 = xsrc[(kc + 1) * 8 + 1];
#pragma unroll
            for (int j = 0; j < 4; j++) wr[j] = wsrc[(kc + 1) * 16 + j];
        }
        __syncthreads();

        const uint32_t* xb = sX + cb * 2304;
        const uint32_t* wb = sW2 + cb * 2 * 2304;
#pragma unroll
        for (int ks = 0; ks < 4; ks++) {
            const int kw = ks * 8 + (lane & 3);
            uint32_t a[2][4];
#pragma unroll
            for (int mt = 0; mt < 2; mt++) {
                int row = wm * 32 + mt * 16 + (lane >> 2);
                a[mt][0] = xb[row * 36 + kw];
                a[mt][1] = xb[(row + 8) * 36 + kw];
                a[mt][2] = xb[row * 36 + kw + 4];
                a[mt][3] = xb[(row + 8) * 36 + kw + 4];
            }
#pragma unroll
            for (int s = 0; s < 2; s++)
#pragma unroll
                for (int nt = 0; nt < 2; nt++) {
                    int n = wn * 16 + nt * 8 + (lane >> 2);
                    uint32_t b[2];
                    b[0] = wb[s * 2304 + n * 36 + kw];
                    b[1] = wb[s * 2304 + n * 36 + kw + 4];
#pragma unroll
                    for (int mt = 0; mt < 2; mt++)
                        mma_f16(acc[mt][nt], a[mt], b);
                }
        }

        if (kc < 31) {
            const int nb = cb ^ 1;
            uint32_t* xd = sX + nb * 2304 + lrow * 36 + lk8;
            xd[0] = xr0.x; xd[1] = xr0.y; xd[2] = xr0.z; xd[3] = xr0.w;
            xd[4] = xr1.x; xd[5] = xr1.y; xd[6] = xr1.z; xd[7] = xr1.w;
            const float* wf = (const float*)wr;
            uint32_t* w0d = sW2 + nb * 2 * 2304 + lrow * 36 + lk8;
            uint32_t* w1d = w0d + 2304;
#pragma unroll
            for (int j = 0; j < 8; j++) {
                float a = wf[2 * j], b = wf[2 * j + 1];
                __half ha = __float2half(a), hb = __float2half(b);
                w0d[j] = packh(ha, hb);
                w1d[j] = packh(__float2half(a - __half2float(ha)),
                               __float2half(b - __half2float(hb)));
            }
        }
    }

    float* outp = g_part + blockIdx.z * (1024 * 256);
    const int r0 = rowbase + wm * 32 + (lane >> 2);
    const int c0 = n0 + wn * 16 + (lane & 3) * 2;
#pragma unroll
    for (int mt = 0; mt < 2; mt++)
#pragma unroll
        for (int nt = 0; nt < 2; nt++) {
            int r = r0 + mt * 16, c = c0 + nt * 8;
            outp[r * 256 + c]           = acc[mt][nt][0];
            outp[r * 256 + c + 1]       = acc[mt][nt][1];
            outp[(r + 8) * 256 + c]     = acc[mt][nt][2];
            outp[(r + 8) * 256 + c + 1] = acc[mt][nt][3];
        }
}

// ---------------------------------------------------------------------------
// Kernel 4: 25-step LIF recurrence, 1024 threads, K-split-4 layer-4 GEMV,
//   split layer-5. Combines fc1 partials + bias into cur3 at load.
// ---------------------------------------------------------------------------
#define REC_W2S (256 * 129)
#define REC_SMEM_BYTES ((REC_W2S + 1280 + 128 + 16 + 256 + 2048 + 1024 + 4096 + 160) * 4)

__global__ void __launch_bounds__(1024, 1) rec_kernel(const float* __restrict__ w2,
                                                      const float* __restrict__ b2,
                                                      const float* __restrict__ w3,
                                                      const float* __restrict__ b3,
                                                      const float* __restrict__ b1,
                                                      float* __restrict__ out) {
    extern __shared__ float smr[];
    float* w2s    = smr;                  // [i*129 + j]
    float* w3s    = w2s + REC_W2S;        // [k*10 + j]
    float* b2s    = w3s + 1280;
    float* b3s    = b2s + 128;
    float* b1s    = b3s + 16;             // [256]
    float* spk3s  = b1s + 256;            // [256][8]
    float* spk4s  = spk3s + 2048;         // [128][8]
    float* part44 = spk4s + 1024;         // [kq][j4][rg][4] = 4096
    float* part5  = part44 + 4096;        // [2][80]

    const int t = threadIdx.x;
    const int rowbase = blockIdx.x * 8;

    for (int idx = t; idx < 128 * 256; idx += 1024) {
        int j = idx >> 8, i = idx & 255;
        w2s[i * 129 + j] = w2[idx];
    }
    for (int idx = t; idx < 1280; idx += 1024) {
        int j = idx >> 7, k = idx & 127;
        w3s[k * 10 + j] = w3[idx];
    }
    if (t < 128) b2s[t] = b2[t];
    if (t < 10)  b3s[t] = b3[t];
    if (t < 256) b1s[t] = b1[t];
    __syncthreads();

    // layer-3: thread owns neuron n3 for 2 rows (rq selects row pair)
    const int n3 = t & 255, rq = t >> 8;
    float mem3[2], c3[2];
    const int QS = 1024 * 256;
#pragma unroll
    for (int r = 0; r < 2; r++) {
        int row = rowbase + rq * 2 + r;
        mem3[r] = 0.f;
        int off = row * 256 + n3;
        c3[r] = ((g_part[off] + g_part[off + QS]) +
                 (g_part[off + 2 * QS] + g_part[off + 3 * QS])) + b1s[n3];
    }
    // layer-4: j4, row group rg, K quarter kq
    const int j4 = t & 127, rg = (t >> 7) & 1, kq = t >> 8;
    float mem4[4] = {0.f, 0.f, 0.f, 0.f};
    const float b2v = b2s[j4];
    // layer-5: threads 0..159 compute partials; 0..79 own state
    float mem5 = 0.f;
    const int rj5 = t % 80, kh5 = (t < 80) ? 0 : 1;
    const int r5 = rj5 / 10, j5 = rj5 % 10;
    const float b3v = (t < 80) ? b3s[j5] : 0.f;

    for (int step = 0; step < NSTEPS; step++) {
        // layer 3 LIF (1024 threads x 2 rows)
        float2 sp;
        {
            float reset0 = (mem3[0] > 1.f) ? 1.f : 0.f;
            float m0 = 0.95f * mem3[0] + c3[0] - reset0;
            mem3[0] = m0; sp.x = (m0 > 1.f) ? 1.f : 0.f;
            float reset1 = (mem3[1] > 1.f) ? 1.f : 0.f;
            float m1 = 0.95f * mem3[1] + c3[1] - reset1;
            mem3[1] = m1; sp.y = (m1 > 1.f) ? 1.f : 0.f;
        }
        *(float2*)&spk3s[n3 * 8 + rq * 2] = sp;
        __syncthreads();

        // layer 4 partial GEMV: quarter K range per thread
        {
            float a4[4] = {0.f, 0.f, 0.f, 0.f};
            const int i0 = kq * 64;
#pragma unroll 4
            for (int i = i0; i < i0 + 64; i++) {
                float w = w2s[i * 129 + j4];
                float4 s = *(const float4*)&spk3s[i * 8 + rg * 4];
                a4[0] += w * s.x; a4[1] += w * s.y; a4[2] += w * s.z; a4[3] += w * s.w;
            }
            *(float4*)&part44[((kq * 256) + (j4 * 2 + rg)) * 4] =
                make_float4(a4[0], a4[1], a4[2], a4[3]);
        }
        __syncthreads();

        // layer 4 combine + LIF (first 256 threads)
        if (t < 256) {
            const int cj = t & 127, crg = t >> 7;
            const int base = (cj * 2 + crg) * 4;
            float4 p0 = *(const float4*)&part44[base];
            float4 p1 = *(const float4*)&part44[1024 + base];
            float4 p2 = *(const float4*)&part44[2048 + base];
            float4 p3 = *(const float4*)&part44[3072 + base];
            float cur[4] = {((p0.x + p1.x) + (p2.x + p3.x)) + b2v,
                            ((p0.y + p1.y) + (p2.y + p3.y)) + b2v,
                            ((p0.z + p1.z) + (p2.z + p3.z)) + b2v,
                            ((p0.w + p1.w) + (p2.w + p3.w)) + b2v};
            float s4[4];
#pragma unroll
            for (int r = 0; r < 4; r++) {
                float reset = (mem4[r] > 1.f) ? 1.f : 0.f;
                float m = 0.95f * mem4[r] + cur[r] - reset;
                mem4[r] = m;
                s4[r] = (m > 1.f) ? 1.f : 0.f;
            }
            *(float4*)&spk4s[cj * 8 + crg * 4] = make_float4(s4[0], s4[1], s4[2], s4[3]);
        }
        __syncthreads();

        // layer 5 partials (threads 0..159)
        if (t < 160) {
            float a5 = 0.f;
            const int k0 = kh5 * 64;
#pragma unroll 8
            for (int k = k0; k < k0 + 64; k++)
                a5 += w3s[k * 10 + j5] * spk4s[k * 8 + r5];
            part5[kh5 * 80 + rj5] = a5;
        }
        __syncthreads();

        // layer 5 combine + LIF + output
        if (t < 80) {
            float a5 = b3v + (part5[t] + part5[80 + t]);
            float reset = (mem5 > 1.f) ? 1.f : 0.f;
            float m = 0.95f * mem5 + a5 - reset;
            mem5 = m;
            out[(step * 1024 + rowbase + r5) * 10 + j5] = (m > 1.f) ? 1.f : 0.f;
        }
        __syncthreads();
    }
}

// ---------------------------------------------------------------------------
extern "C" void kernel_launch(void* const* d_in, const int* in_sizes, int n_in,
                              void* d_out, int out_size) {
    const float* x       = (const float*)d_in[0];
    const float* conv1_w = (const float*)d_in[1];
    const float* conv1_b = (const float*)d_in[2];
    const float* conv2_w = (const float*)d_in[3];
    const float* conv2_b = (const float*)d_in[4];
    const float* fc1_w   = (const float*)d_in[5];
    const float* fc1_b   = (const float*)d_in[6];
    const float* fc2_w   = (const float*)d_in[7];
    const float* fc2_b   = (const float*)d_in[8];
    const float* fc3_w   = (const float*)d_in[9];
    const float* fc3_b   = (const float*)d_in[10];
    float* out = (float*)d_out;

    cudaFuncSetAttribute(conv2_mma, cudaFuncAttributeMaxDynamicSharedMemorySize,
                         C2_SMEM);
    cudaFuncSetAttribute(fc1_mma, cudaFuncAttributeMaxDynamicSharedMemorySize,
                         FC1_SMEM);
    cudaFuncSetAttribute(rec_kernel, cudaFuncAttributeMaxDynamicSharedMemorySize,
                         REC_SMEM_BYTES);

    conv1_kernel<<<BATCH, 256>>>(x, conv1_w, conv1_b);
    conv2_mma<<<148, 256, C2_SMEM>>>(conv2_w, conv2_b);
    fc1_mma<<<dim3(16, 4, 4), 256, FC1_SMEM>>>(fc1_w);
    rec_kernel<<<128, 1024, REC_SMEM_BYTES>>>(fc2_w, fc2_b, fc3_w, fc3_b, fc1_b, out);
}

// round 8
// speedup vs baseline: 3.2373x; 1.2333x over previous
#include <cuda_runtime.h>
#include <cuda_fp16.h>
#include <cstdint>

#define BATCH 1024
#define NSTEPS 25

// scratch (device globals)
__device__ float  g_c1[BATCH * 32 * 32 * 16];     // pooled spikes after conv1
__device__ __half g_xh[BATCH * 8192];             // pooled spikes after conv2 (fp16, exact)
__device__ float  g_part[4 * 1024 * 256];         // fc1 K-split partials

// ---------------------------------------------------------------------------
// mma.sync m16n8k16 fp16 (baseline PTX)
// ---------------------------------------------------------------------------
__device__ __forceinline__ void mma_f16(float* d, const uint32_t* a, const uint32_t* b) {
    asm volatile(
        "mma.sync.aligned.m16n8k16.row.col.f32.f16.f16.f32 "
        "{%0,%1,%2,%3}, {%4,%5,%6,%7}, {%8,%9}, {%0,%1,%2,%3};"
        : "+f"(d[0]), "+f"(d[1]), "+f"(d[2]), "+f"(d[3])
        : "r"(a[0]), "r"(a[1]), "r"(a[2]), "r"(a[3]), "r"(b[0]), "r"(b[1]));
}
__device__ __forceinline__ uint32_t packh(__half a, __half b) {
    return (uint32_t)__half_as_ushort(a) | ((uint32_t)__half_as_ushort(b) << 16);
}

// ---------------------------------------------------------------------------
// Kernel 1: conv1 (1->32, 3x3 SAME) + spike + pool  (proven R1 version)
// ---------------------------------------------------------------------------
__global__ void __launch_bounds__(256) conv1_kernel(const float* __restrict__ x,
                                                    const float* __restrict__ w1,
                                                    const float* __restrict__ b1) {
    __shared__ float sIn[66 * 34];
    __shared__ float sW[32 * 9];
    __shared__ float sB[32];
    const int t = threadIdx.x;
    const int img = blockIdx.x;

    for (int i = t; i < 66 * 34; i += 256) sIn[i] = 0.f;
    for (int i = t; i < 288; i += 256) sW[i] = w1[i];
    if (t < 32) sB[t] = b1[t];
    __syncthreads();

    const float* xi = x + img * 2048;
    for (int i = t; i < 2048; i += 256) {
        int y = i >> 5, xc = i & 31;
        sIn[(y + 1) * 34 + (xc + 1)] = xi[i];
    }
    __syncthreads();

    for (int cellBase = 0; cellBase < 512; cellBase += 256) {
        int cell = cellBase + t;
        int ph = cell >> 4, pw = cell & 15;
        float in[4][4];
#pragma unroll
        for (int r = 0; r < 4; r++)
#pragma unroll
            for (int c = 0; c < 4; c++)
                in[r][c] = sIn[(2 * ph + r) * 34 + (2 * pw + c)];

        for (int ch = 0; ch < 32; ch++) {
            float wv[9];
#pragma unroll
            for (int k = 0; k < 9; k++) wv[k] = sW[ch * 9 + k];
            float bb = sB[ch];
            float cnt = 0.f;
#pragma unroll
            for (int dy = 0; dy < 2; dy++)
#pragma unroll
                for (int dx = 0; dx < 2; dx++) {
                    float s = bb;
#pragma unroll
                    for (int ky = 0; ky < 3; ky++)
#pragma unroll
                        for (int kx = 0; kx < 3; kx++)
                            s += wv[ky * 3 + kx] * in[dy + ky][dx + kx];
                    cnt += (s > 1.f) ? 1.f : 0.f;
                }
            g_c1[((img * 32 + ch) * 32 + ph) * 16 + pw] = cnt * 0.25f;
        }
    }
}

// ---------------------------------------------------------------------------
// Kernel 2: conv2 via mma.sync fp16 2-split (R7 version)
// ---------------------------------------------------------------------------
#define C2_AF_BYTES 73728                     // 2*4*18*128 u32
#define C2_IN_BYTES (34 * 18 * 48 * 2)        // 58752
#define C2_SMEM (C2_AF_BYTES + C2_IN_BYTES + 256)

__global__ void __launch_bounds__(256, 1) conv2_mma(const float* __restrict__ w2,
                                                    const float* __restrict__ b2) {
    extern __shared__ char sm[];
    uint32_t* sAf = (uint32_t*)sm;
    __half* sIn = (__half*)(sm + C2_AF_BYTES);

    const int t = threadIdx.x;
    const int lane = t & 31, wid = t >> 5;

    for (int i = t; i < C2_IN_BYTES / 4; i += 256) ((uint32_t*)sIn)[i] = 0u;

    for (int idx = t; idx < 4 * 18 * 32 * 4; idx += 256) {
        int r = idx & 3, ln = (idx >> 2) & 31, ks = (idx >> 7) % 18, mt = idx / (128 * 18);
        int oc = mt * 16 + (ln >> 2) + (r & 1) * 8;
        int kk = (ln & 3) * 2 + (r >> 1) * 8;
        int tap = ks >> 1, ci0 = (ks & 1) * 16;
        float w0 = w2[oc * 288 + (ci0 + kk) * 9 + tap];
        float w1v = w2[oc * 288 + (ci0 + kk + 1) * 9 + tap];
#pragma unroll
        for (int s = 0; s < 2; s++) {
            __half h0 = __float2half(w0);
            __half h1 = __float2half(w1v);
            w0 -= __half2float(h0);
            w1v -= __half2float(h1);
            sAf[((s * 4 + mt) * 18 + ks) * 128 + ln * 4 + r] = packh(h0, h1);
        }
    }

    float biasr[4][2];
#pragma unroll
    for (int mt = 0; mt < 4; mt++) {
        biasr[mt][0] = b2[mt * 16 + (lane >> 2)];
        biasr[mt][1] = b2[mt * 16 + (lane >> 2) + 8];
    }

    int posoff[8];
#pragma unroll
    for (int nt = 0; nt < 8; nt++) {
        int pos = wid * 64 + nt * 8 + (lane >> 2);
        posoff[nt] = ((pos >> 4) * 18 + (pos & 15)) * 48;
    }

    for (int img = blockIdx.x; img < BATCH; img += gridDim.x) {
        const float* in = g_c1 + img * 16384;
        for (int i = t; i < 4096; i += 256) {
            float4 v = ((const float4*)in)[i];
            int e = i * 4, ci = e >> 9, rem = e & 511, h = rem >> 4, w = rem & 15;
            int np = (ci & 16) + ((ci & 6) << 1) + (ci & 1) + (((ci >> 3) & 1) << 1);
            __half* p = sIn + ((h + 1) * 18 + (w + 1)) * 48 + np;
            p[0]   = __float2half(v.x);
            p[48]  = __float2half(v.y);
            p[96]  = __float2half(v.z);
            p[144] = __float2half(v.w);
        }
        __syncthreads();

        float acc[4][8][4];
#pragma unroll
        for (int mt = 0; mt < 4; mt++)
#pragma unroll
            for (int nt = 0; nt < 8; nt++)
#pragma unroll
                for (int q = 0; q < 4; q++) acc[mt][nt][q] = 0.f;

#pragma unroll 2
        for (int ks = 0; ks < 18; ks++) {
            int tap = ks >> 1, ci0 = (ks & 1) * 16;
            int dy = tap / 3, dx = tap - dy * 3;
            int toff = (dy * 18 + dx) * 48 + ci0 + (lane & 3) * 4;

            uint32_t bfr[8][2];
#pragma unroll
            for (int nt = 0; nt < 8; nt++) {
                uint2 bv = *(const uint2*)(sIn + posoff[nt] + toff);
                bfr[nt][0] = bv.x; bfr[nt][1] = bv.y;
            }
#pragma unroll
            for (int s = 0; s < 2; s++)
#pragma unroll
                for (int mt = 0; mt < 4; mt++) {
                    uint4 av = ((const uint4*)(sAf + ((s * 4 + mt) * 18 + ks) * 128))[lane];
                    uint32_t a[4] = {av.x, av.y, av.z, av.w};
#pragma unroll
                    for (int nt = 0; nt < 8; nt++)
                        mma_f16(acc[mt][nt], a, bfr[nt]);
                }
        }

        __half* xout = g_xh + img * 8192;
#pragma unroll
        for (int mt = 0; mt < 4; mt++)
#pragma unroll
            for (int rh = 0; rh < 2; rh++) {
                int ch = mt * 16 + (lane >> 2) + rh * 8;
                float bv = biasr[mt][rh];
#pragma unroll
                for (int np2 = 0; np2 < 4; np2++) {
                    int nt = (np2 & 1) + (np2 >> 1) * 4;   // {0,1,4,5}
                    float s0 = (acc[mt][nt][rh * 2]         + bv > 1.f) ? 1.f : 0.f;
                    float s1 = (acc[mt][nt][rh * 2 + 1]     + bv > 1.f) ? 1.f : 0.f;
                    float s2 = (acc[mt][nt + 2][rh * 2]     + bv > 1.f) ? 1.f : 0.f;
                    float s3 = (acc[mt][nt + 2][rh * 2 + 1] + bv > 1.f) ? 1.f : 0.f;
                    int h = wid * 4 + (nt >> 1);
                    int ph = h >> 1;
                    int pw = (nt & 1) * 4 + (lane & 3);
                    xout[ch * 128 + ph * 8 + pw] = __float2half((s0 + s1 + s2 + s3) * 0.25f);
                }
            }
        __syncthreads();
    }
}

// ---------------------------------------------------------------------------
// Kernel 3: fc1 via mma.sync fp16 2-split, split-K=4, double-buffered (R7)
// ---------------------------------------------------------------------------
#define FC1_SMEM ((2 * 2304 + 4 * 2304) * 4)   // 55296 B

__global__ void __launch_bounds__(256) fc1_mma(const float* __restrict__ W) {
    extern __shared__ uint32_t smf[];
    uint32_t* sX = smf;
    uint32_t* sW2 = smf + 2 * 2304;

    const int t = threadIdx.x;
    const int lane = t & 31, wid = t >> 5;
    const int wm = wid & 1, wn = wid >> 1;
    const int rowbase = blockIdx.x * 64;
    const int n0 = blockIdx.y * 64;
    const int k0 = blockIdx.z * 2048;

    const int lrow = t >> 2, lk16 = (t & 3) * 16, lk8 = (t & 3) * 8;

    const uint4* xsrc = (const uint4*)(g_xh + (rowbase + lrow) * 8192 + k0 + lk16);
    const float4* wsrc = (const float4*)(W + (n0 + lrow) * 8192 + k0 + lk16);

    float acc[2][2][4];
#pragma unroll
    for (int mt = 0; mt < 2; mt++)
#pragma unroll
        for (int nt = 0; nt < 2; nt++)
#pragma unroll
            for (int q = 0; q < 4; q++) acc[mt][nt][q] = 0.f;

    uint4 xr0, xr1;
    float4 wr[4];

    xr0 = xsrc[0]; xr1 = xsrc[1];
#pragma unroll
    for (int j = 0; j < 4; j++) wr[j] = wsrc[j];

    {
        uint32_t* xd = sX + lrow * 36 + lk8;
        xd[0] = xr0.x; xd[1] = xr0.y; xd[2] = xr0.z; xd[3] = xr0.w;
        xd[4] = xr1.x; xd[5] = xr1.y; xd[6] = xr1.z; xd[7] = xr1.w;
        const float* wf = (const float*)wr;
        uint32_t* w0d = sW2 + lrow * 36 + lk8;
        uint32_t* w1d = sW2 + 2304 + lrow * 36 + lk8;
#pragma unroll
        for (int j = 0; j < 8; j++) {
            float a = wf[2 * j], b = wf[2 * j + 1];
            __half ha = __float2half(a), hb = __float2half(b);
            w0d[j] = packh(ha, hb);
            w1d[j] = packh(__float2half(a - __half2float(ha)),
                           __float2half(b - __half2float(hb)));
        }
    }

    for (int kc = 0; kc < 32; kc++) {
        const int cb = kc & 1;
        if (kc < 31) {
            xr0 = xsrc[(kc + 1) * 8]; xr1 = xsrc[(kc + 1) * 8 + 1];
#pragma unroll
            for (int j = 0; j < 4; j++) wr[j] = wsrc[(kc + 1) * 16 + j];
        }
        __syncthreads();

        const uint32_t* xb = sX + cb * 2304;
        const uint32_t* wb = sW2 + cb * 2 * 2304;
#pragma unroll
        for (int ks = 0; ks < 4; ks++) {
            const int kw = ks * 8 + (lane & 3);
            uint32_t a[2][4];
#pragma unroll
            for (int mt = 0; mt < 2; mt++) {
                int row = wm * 32 + mt * 16 + (lane >> 2);
                a[mt][0] = xb[row * 36 + kw];
                a[mt][1] = xb[(row + 8) * 36 + kw];
                a[mt][2] = xb[row * 36 + kw + 4];
                a[mt][3] = xb[(row + 8) * 36 + kw + 4];
            }
#pragma unroll
            for (int s = 0; s < 2; s++)
#pragma unroll
                for (int nt = 0; nt < 2; nt++) {
                    int n = wn * 16 + nt * 8 + (lane >> 2);
                    uint32_t b[2];
                    b[0] = wb[s * 2304 + n * 36 + kw];
                    b[1] = wb[s * 2304 + n * 36 + kw + 4];
#pragma unroll
                    for (int mt = 0; mt < 2; mt++)
                        mma_f16(acc[mt][nt], a[mt], b);
                }
        }

        if (kc < 31) {
            const int nb = cb ^ 1;
            uint32_t* xd = sX + nb * 2304 + lrow * 36 + lk8;
            xd[0] = xr0.x; xd[1] = xr0.y; xd[2] = xr0.z; xd[3] = xr0.w;
            xd[4] = xr1.x; xd[5] = xr1.y; xd[6] = xr1.z; xd[7] = xr1.w;
            const float* wf = (const float*)wr;
            uint32_t* w0d = sW2 + nb * 2 * 2304 + lrow * 36 + lk8;
            uint32_t* w1d = w0d + 2304;
#pragma unroll
            for (int j = 0; j < 8; j++) {
                float a = wf[2 * j], b = wf[2 * j + 1];
                __half ha = __float2half(a), hb = __float2half(b);
                w0d[j] = packh(ha, hb);
                w1d[j] = packh(__float2half(a - __half2float(ha)),
                               __float2half(b - __half2float(hb)));
            }
        }
    }

    float* outp = g_part + blockIdx.z * (1024 * 256);
    const int r0 = rowbase + wm * 32 + (lane >> 2);
    const int c0 = n0 + wn * 16 + (lane & 3) * 2;
#pragma unroll
    for (int mt = 0; mt < 2; mt++)
#pragma unroll
        for (int nt = 0; nt < 2; nt++) {
            int r = r0 + mt * 16, c = c0 + nt * 8;
            outp[r * 256 + c]           = acc[mt][nt][0];
            outp[r * 256 + c + 1]       = acc[mt][nt][1];
            outp[(r + 8) * 256 + c]     = acc[mt][nt][2];
            outp[(r + 8) * 256 + c + 1] = acc[mt][nt][3];
        }
}

// ---------------------------------------------------------------------------
// Kernel 4: 25-step LIF recurrence. Layer-4 GEMV on tensor cores:
//   per step, [8x256]x[256x128] = 16 warps x (16 ks x 2 splits) m16n8k16 mma.
//   fc2_w pre-staged in mma B-fragment layout (fp16 2-split, 128 KB smem).
//   Layer-3 spikes stored fp16 in A-fragment-friendly layout (stride 264).
//   mem4 state lives in D-fragment lanes' registers. 3 syncs/step.
// ---------------------------------------------------------------------------
#define REC_SMEM_BYTES (36688 * 4)

__global__ void __launch_bounds__(1024, 1) rec_kernel(const float* __restrict__ w2,
                                                      const float* __restrict__ b2,
                                                      const float* __restrict__ w3,
                                                      const float* __restrict__ b3,
                                                      const float* __restrict__ b1,
                                                      float* __restrict__ out) {
    extern __shared__ uint32_t smu[];
    uint32_t* w4f   = smu;                          // 32768 u32: fc2_w frags
    float* w3s      = (float*)(smu + 32768);        // 1280
    float* b2s      = w3s + 1280;                   // 128
    float* b3s      = b2s + 128;                    // 16
    float* b1s      = b3s + 16;                     // 256
    __half* spk3h   = (__half*)(b1s + 256);         // 8 rows x 264 halves
    float* spk4s    = (float*)((uint32_t*)(b1s + 256) + 1056);  // 1024
    float* part5    = spk4s + 1024;                 // 160

    const int t = threadIdx.x;
    const int lane = t & 31, wid = t >> 5;
    const int rowbase = blockIdx.x * 8;

    // build fc2_w fragments: idx = w*2048 + ks*128 + s*64 + ln*2 + reg
    for (int idx = t; idx < 32768; idx += 1024) {
        int reg = idx & 1, ln = (idx >> 1) & 31, s = (idx >> 6) & 1;
        int ks = (idx >> 7) & 15, w = idx >> 11;
        int n = w * 8 + (ln >> 2);
        int kb = ks * 16 + (ln & 3) * 2 + reg * 8;
        float w0 = w2[n * 256 + kb], w1v = w2[n * 256 + kb + 1];
        __half h0, h1;
        if (s == 0) { h0 = __float2half(w0); h1 = __float2half(w1v); }
        else {
            h0 = __float2half(w0 - __half2float(__float2half(w0)));
            h1 = __float2half(w1v - __half2float(__float2half(w1v)));
        }
        w4f[idx] = packh(h0, h1);
    }
    for (int idx = t; idx < 1280; idx += 1024) {
        int j = idx >> 7, k = idx & 127;
        w3s[k * 10 + j] = w3[idx];
    }
    if (t < 128) b2s[t] = b2[t];
    if (t < 10)  b3s[t] = b3[t];
    if (t < 256) b1s[t] = b1[t];
    __syncthreads();

    // layer-3: thread owns neuron n3 for rows 2rq, 2rq+1
    const int n3 = t & 255, rq = t >> 8;
    float mem3[2], c3[2];
    const int QS = 1024 * 256;
#pragma unroll
    for (int r = 0; r < 2; r++) {
        int row = rowbase + rq * 2 + r;
        mem3[r] = 0.f;
        int off = row * 256 + n3;
        c3[r] = ((g_part[off] + g_part[off + QS]) +
                 (g_part[off + 2 * QS] + g_part[off + 3 * QS])) + b1s[n3];
    }

    // layer-4: warps 0-15, warp = n-tile; lane owns (row=g4, cols j0,j0+1)
    const int g4 = lane >> 2, q4 = lane & 3;
    float mem40 = 0.f, mem41 = 0.f;
    float b2v0 = 0.f, b2v1 = 0.f;
    if (wid < 16) {
        b2v0 = b2s[wid * 8 + q4 * 2];
        b2v1 = b2s[wid * 8 + q4 * 2 + 1];
    }
    // layer-5
    float mem5 = 0.f;
    const int rj5 = t % 80, kh5 = (t < 80) ? 0 : 1;
    const int r5 = rj5 / 10, j5 = rj5 % 10;
    const float b3v = (t < 80) ? b3s[j5] : 0.f;

    for (int step = 0; step < NSTEPS; step++) {
        // layer 3 LIF -> fp16 spikes in A-frag layout
#pragma unroll
        for (int r = 0; r < 2; r++) {
            float reset = (mem3[r] > 1.f) ? 1.f : 0.f;
            float m = 0.95f * mem3[r] + c3[r] - reset;
            mem3[r] = m;
            spk3h[(rq * 2 + r) * 264 + n3] = __float2half((m > 1.f) ? 1.f : 0.f);
        }
        __syncthreads();

        // layer 4: tensor-core GEMV (warps 0-15)
        if (wid < 16) {
            float c[4] = {0.f, 0.f, 0.f, 0.f};
            uint32_t a[4];
            a[1] = 0u; a[3] = 0u;   // rows 8-15 are zero padding
            const __half* ab = spk3h + g4 * 264 + q4 * 2;
            const uint32_t* wb = w4f + wid * 2048;
#pragma unroll
            for (int ks = 0; ks < 16; ks++) {
                a[0] = *(const uint32_t*)(ab + ks * 16);
                a[2] = *(const uint32_t*)(ab + ks * 16 + 8);
                uint2 bv0 = *(const uint2*)(wb + ks * 128 + lane * 2);
                mma_f16(c, a, (const uint32_t*)&bv0);
                uint2 bv1 = *(const uint2*)(wb + ks * 128 + 64 + lane * 2);
                mma_f16(c, a, (const uint32_t*)&bv1);
            }
            // LIF on (row g4, cols j0, j0+1)
            float cur0 = c[0] + b2v0;
            float cur1 = c[1] + b2v1;
            float reset0 = (mem40 > 1.f) ? 1.f : 0.f;
            float m0 = 0.95f * mem40 + cur0 - reset0;
            mem40 = m0;
            float reset1 = (mem41 > 1.f) ? 1.f : 0.f;
            float m1 = 0.95f * mem41 + cur1 - reset1;
            mem41 = m1;
            int j0 = wid * 8 + q4 * 2;
            spk4s[j0 * 8 + g4]       = (m0 > 1.f) ? 1.f : 0.f;
            spk4s[(j0 + 1) * 8 + g4] = (m1 > 1.f) ? 1.f : 0.f;
        }
        __syncthreads();

        // layer 5 partials (threads 0..159)
        if (t < 160) {
            float a5 = 0.f;
            const int k0 = kh5 * 64;
#pragma unroll 8
            for (int k = k0; k < k0 + 64; k++)
                a5 += w3s[k * 10 + j5] * spk4s[k * 8 + r5];
            part5[kh5 * 80 + rj5] = a5;
        }
        __syncthreads();

        // layer 5 combine + LIF + output
        if (t < 80) {
            float a5 = b3v + (part5[t] + part5[80 + t]);
            float reset = (mem5 > 1.f) ? 1.f : 0.f;
            float m = 0.95f * mem5 + a5 - reset;
            mem5 = m;
            out[(step * 1024 + rowbase + r5) * 10 + j5] = (m > 1.f) ? 1.f : 0.f;
        }
        // no 4th sync needed: part5/spk4s rewrites are fenced by the two
        // syncs that precede them on every path in the next iteration.
    }
}

// ---------------------------------------------------------------------------
extern "C" void kernel_launch(void* const* d_in, const int* in_sizes, int n_in,
                              void* d_out, int out_size) {
    const float* x       = (const float*)d_in[0];
    const float* conv1_w = (const float*)d_in[1];
    const float* conv1_b = (const float*)d_in[2];
    const float* conv2_w = (const float*)d_in[3];
    const float* conv2_b = (const float*)d_in[4];
    const float* fc1_w   = (const float*)d_in[5];
    const float* fc1_b   = (const float*)d_in[6];
    const float* fc2_w   = (const float*)d_in[7];
    const float* fc2_b   = (const float*)d_in[8];
    const float* fc3_w   = (const float*)d_in[9];
    const float* fc3_b   = (const float*)d_in[10];
    float* out = (float*)d_out;

    cudaFuncSetAttribute(conv2_mma, cudaFuncAttributeMaxDynamicSharedMemorySize,
                         C2_SMEM);
    cudaFuncSetAttribute(fc1_mma, cudaFuncAttributeMaxDynamicSharedMemorySize,
                         FC1_SMEM);
    cudaFuncSetAttribute(rec_kernel, cudaFuncAttributeMaxDynamicSharedMemorySize,
                         REC_SMEM_BYTES);

    conv1_kernel<<<BATCH, 256>>>(x, conv1_w, conv1_b);
    conv2_mma<<<148, 256, C2_SMEM>>>(conv2_w, conv2_b);
    fc1_mma<<<dim3(16, 4, 4), 256, FC1_SMEM>>>(fc1_w);
    rec_kernel<<<128, 1024, REC_SMEM_BYTES>>>(fc2_w, fc2_b, fc3_w, fc3_b, fc1_b, out);
}

// round 9
// speedup vs baseline: 3.2631x; 1.0080x over previous
#include <cuda_runtime.h>
#include <cuda_fp16.h>
#include <cstdint>

#define BATCH 1024
#define NSTEPS 25

// scratch (device globals)
__device__ float  g_c1[BATCH * 32 * 32 * 16];     // pooled spikes after conv1
__device__ __half g_xh[BATCH * 8192];             // pooled spikes after conv2 (fp16, exact)
__device__ float  g_part[4 * 1024 * 256];         // fc1 K-split partials

// ---------------------------------------------------------------------------
// mma.sync m16n8k16 fp16 (baseline PTX)
// ---------------------------------------------------------------------------
__device__ __forceinline__ void mma_f16(float* d, const uint32_t* a, const uint32_t* b) {
    asm volatile(
        "mma.sync.aligned.m16n8k16.row.col.f32.f16.f16.f32 "
        "{%0,%1,%2,%3}, {%4,%5,%6,%7}, {%8,%9}, {%0,%1,%2,%3};"
        : "+f"(d[0]), "+f"(d[1]), "+f"(d[2]), "+f"(d[3])
        : "r"(a[0]), "r"(a[1]), "r"(a[2]), "r"(a[3]), "r"(b[0]), "r"(b[1]));
}
__device__ __forceinline__ uint32_t packh(__half a, __half b) {
    return (uint32_t)__half_as_ushort(a) | ((uint32_t)__half_as_ushort(b) << 16);
}

// ---------------------------------------------------------------------------
// Kernel 1: conv1 (1->32, 3x3 SAME) + spike + pool  (proven R1 version)
// ---------------------------------------------------------------------------
__global__ void __launch_bounds__(256) conv1_kernel(const float* __restrict__ x,
                                                    const float* __restrict__ w1,
                                                    const float* __restrict__ b1) {
    __shared__ float sIn[66 * 34];
    __shared__ float sW[32 * 9];
    __shared__ float sB[32];
    const int t = threadIdx.x;
    const int img = blockIdx.x;

    for (int i = t; i < 66 * 34; i += 256) sIn[i] = 0.f;
    for (int i = t; i < 288; i += 256) sW[i] = w1[i];
    if (t < 32) sB[t] = b1[t];
    __syncthreads();

    const float* xi = x + img * 2048;
    for (int i = t; i < 2048; i += 256) {
        int y = i >> 5, xc = i & 31;
        sIn[(y + 1) * 34 + (xc + 1)] = xi[i];
    }
    __syncthreads();

    for (int cellBase = 0; cellBase < 512; cellBase += 256) {
        int cell = cellBase + t;
        int ph = cell >> 4, pw = cell & 15;
        float in[4][4];
#pragma unroll
        for (int r = 0; r < 4; r++)
#pragma unroll
            for (int c = 0; c < 4; c++)
                in[r][c] = sIn[(2 * ph + r) * 34 + (2 * pw + c)];

        for (int ch = 0; ch < 32; ch++) {
            float wv[9];
#pragma unroll
            for (int k = 0; k < 9; k++) wv[k] = sW[ch * 9 + k];
            float bb = sB[ch];
            float cnt = 0.f;
#pragma unroll
            for (int dy = 0; dy < 2; dy++)
#pragma unroll
                for (int dx = 0; dx < 2; dx++) {
                    float s = bb;
#pragma unroll
                    for (int ky = 0; ky < 3; ky++)
#pragma unroll
                        for (int kx = 0; kx < 3; kx++)
                            s += wv[ky * 3 + kx] * in[dy + ky][dx + kx];
                    cnt += (s > 1.f) ? 1.f : 0.f;
                }
            g_c1[((img * 32 + ch) * 32 + ph) * 16 + pw] = cnt * 0.25f;
        }
    }
}

// ---------------------------------------------------------------------------
// Kernel 2: conv2 via mma.sync fp16 2-split — 512 threads / 16 warps.
//   Warp grid: wm (2 M-halves: mt = wm*2+{0,1}) x wn (8 N-groups of 64 pos).
//   4 warps/SMSP for LDS latency hiding; A loads halve per warp.
// ---------------------------------------------------------------------------
#define C2_AF_BYTES 73728                     // 2*4*18*128 u32
#define C2_IN_BYTES (34 * 18 * 48 * 2)        // 58752
#define C2_SMEM (C2_AF_BYTES + C2_IN_BYTES + 256)

__global__ void __launch_bounds__(512, 1) conv2_mma(const float* __restrict__ w2,
                                                    const float* __restrict__ b2) {
    extern __shared__ char sm[];
    uint32_t* sAf = (uint32_t*)sm;
    __half* sIn = (__half*)(sm + C2_AF_BYTES);

    const int t = threadIdx.x;
    const int lane = t & 31, wid = t >> 5;
    const int wm = wid & 1, wn = wid >> 1;

    for (int i = t; i < C2_IN_BYTES / 4; i += 512) ((uint32_t*)sIn)[i] = 0u;

    // weight fragments, 2 fp16 splits, K order (tap, ci)
    for (int idx = t; idx < 4 * 18 * 32 * 4; idx += 512) {
        int r = idx & 3, ln = (idx >> 2) & 31, ks = (idx >> 7) % 18, mt = idx / (128 * 18);
        int oc = mt * 16 + (ln >> 2) + (r & 1) * 8;
        int kk = (ln & 3) * 2 + (r >> 1) * 8;
        int tap = ks >> 1, ci0 = (ks & 1) * 16;
        float w0 = w2[oc * 288 + (ci0 + kk) * 9 + tap];
        float w1v = w2[oc * 288 + (ci0 + kk + 1) * 9 + tap];
#pragma unroll
        for (int s = 0; s < 2; s++) {
            __half h0 = __float2half(w0);
            __half h1 = __float2half(w1v);
            w0 -= __half2float(h0);
            w1v -= __half2float(h1);
            sAf[((s * 4 + mt) * 18 + ks) * 128 + ln * 4 + r] = packh(h0, h1);
        }
    }

    float biasr[2][2];
#pragma unroll
    for (int ml = 0; ml < 2; ml++) {
        int mt = wm * 2 + ml;
        biasr[ml][0] = b2[mt * 16 + (lane >> 2)];
        biasr[ml][1] = b2[mt * 16 + (lane >> 2) + 8];
    }

    int posoff[8];
#pragma unroll
    for (int nt = 0; nt < 8; nt++) {
        int pos = wn * 64 + nt * 8 + (lane >> 2);
        posoff[nt] = ((pos >> 4) * 18 + (pos & 15)) * 48;
    }

    for (int img = blockIdx.x; img < BATCH; img += gridDim.x) {
        // stage input channel-interleaved with halo
        const float* in = g_c1 + img * 16384;
        for (int i = t; i < 4096; i += 512) {
            float4 v = ((const float4*)in)[i];
            int e = i * 4, ci = e >> 9, rem = e & 511, h = rem >> 4, w = rem & 15;
            int np = (ci & 16) + ((ci & 6) << 1) + (ci & 1) + (((ci >> 3) & 1) << 1);
            __half* p = sIn + ((h + 1) * 18 + (w + 1)) * 48 + np;
            p[0]   = __float2half(v.x);
            p[48]  = __float2half(v.y);
            p[96]  = __float2half(v.z);
            p[144] = __float2half(v.w);
        }
        __syncthreads();

        float acc[2][8][4];
#pragma unroll
        for (int ml = 0; ml < 2; ml++)
#pragma unroll
            for (int nt = 0; nt < 8; nt++)
#pragma unroll
                for (int q = 0; q < 4; q++) acc[ml][nt][q] = 0.f;

#pragma unroll 2
        for (int ks = 0; ks < 18; ks++) {
            int tap = ks >> 1, ci0 = (ks & 1) * 16;
            int dy = tap / 3, dx = tap - dy * 3;
            int toff = (dy * 18 + dx) * 48 + ci0 + (lane & 3) * 4;

            uint32_t bfr[8][2];
#pragma unroll
            for (int nt = 0; nt < 8; nt++) {
                uint2 bv = *(const uint2*)(sIn + posoff[nt] + toff);
                bfr[nt][0] = bv.x; bfr[nt][1] = bv.y;
            }
#pragma unroll
            for (int s = 0; s < 2; s++)
#pragma unroll
                for (int ml = 0; ml < 2; ml++) {
                    int mt = wm * 2 + ml;
                    uint4 av = ((const uint4*)(sAf + ((s * 4 + mt) * 18 + ks) * 128))[lane];
                    uint32_t a[4] = {av.x, av.y, av.z, av.w};
#pragma unroll
                    for (int nt = 0; nt < 8; nt++)
                        mma_f16(acc[ml][nt], a, bfr[nt]);
                }
        }

        __half* xout = g_xh + img * 8192;
#pragma unroll
        for (int ml = 0; ml < 2; ml++)
#pragma unroll
            for (int rh = 0; rh < 2; rh++) {
                int ch = (wm * 2 + ml) * 16 + (lane >> 2) + rh * 8;
                float bv = biasr[ml][rh];
#pragma unroll
                for (int np2 = 0; np2 < 4; np2++) {
                    int nt = (np2 & 1) + (np2 >> 1) * 4;   // {0,1,4,5}
                    float s0 = (acc[ml][nt][rh * 2]         + bv > 1.f) ? 1.f : 0.f;
                    float s1 = (acc[ml][nt][rh * 2 + 1]     + bv > 1.f) ? 1.f : 0.f;
                    float s2 = (acc[ml][nt + 2][rh * 2]     + bv > 1.f) ? 1.f : 0.f;
                    float s3 = (acc[ml][nt + 2][rh * 2 + 1] + bv > 1.f) ? 1.f : 0.f;
                    int h = wn * 4 + (nt >> 1);
                    int ph = h >> 1;
                    int pw = (nt & 1) * 4 + (lane & 3);
                    xout[ch * 128 + ph * 8 + pw] = __float2half((s0 + s1 + s2 + s3) * 0.25f);
                }
            }
        __syncthreads();
    }
}

// ---------------------------------------------------------------------------
// Kernel 3: fc1 via mma.sync fp16 2-split, split-K=4, double-buffered (R7)
// ---------------------------------------------------------------------------
#define FC1_SMEM ((2 * 2304 + 4 * 2304) * 4)   // 55296 B

__global__ void __launch_bounds__(256) fc1_mma(const float* __restrict__ W) {
    extern __shared__ uint32_t smf[];
    uint32_t* sX = smf;
    uint32_t* sW2 = smf + 2 * 2304;

    const int t = threadIdx.x;
    const int lane = t & 31, wid = t >> 5;
    const int wm = wid & 1, wn = wid >> 1;
    const int rowbase = blockIdx.x * 64;
    const int n0 = blockIdx.y * 64;
    const int k0 = blockIdx.z * 2048;

    const int lrow = t >> 2, lk16 = (t & 3) * 16, lk8 = (t & 3) * 8;

    const uint4* xsrc = (const uint4*)(g_xh + (rowbase + lrow) * 8192 + k0 + lk16);
    const float4* wsrc = (const float4*)(W + (n0 + lrow) * 8192 + k0 + lk16);

    float acc[2][2][4];
#pragma unroll
    for (int mt = 0; mt < 2; mt++)
#pragma unroll
        for (int nt = 0; nt < 2; nt++)
#pragma unroll
            for (int q = 0; q < 4; q++) acc[mt][nt][q] = 0.f;

    uint4 xr0, xr1;
    float4 wr[4];

    xr0 = xsrc[0]; xr1 = xsrc[1];
#pragma unroll
    for (int j = 0; j < 4; j++) wr[j] = wsrc[j];

    {
        uint32_t* xd = sX + lrow * 36 + lk8;
        xd[0] = xr0.x; xd[1] = xr0.y; xd[2] = xr0.z; xd[3] = xr0.w;
        xd[4] = xr1.x; xd[5] = xr1.y; xd[6] = xr1.z; xd[7] = xr1.w;
        const float* wf = (const float*)wr;
        uint32_t* w0d = sW2 + lrow * 36 + lk8;
        uint32_t* w1d = sW2 + 2304 + lrow * 36 + lk8;
#pragma unroll
        for (int j = 0; j < 8; j++) {
            float a = wf[2 * j], b = wf[2 * j + 1];
            __half ha = __float2half(a), hb = __float2half(b);
            w0d[j] = packh(ha, hb);
            w1d[j] = packh(__float2half(a - __half2float(ha)),
                           __float2half(b - __half2float(hb)));
        }
    }

    for (int kc = 0; kc < 32; kc++) {
        const int cb = kc & 1;
        if (kc < 31) {
            xr0 = xsrc[(kc + 1) * 8]; xr1 = xsrc[(kc + 1) * 8 + 1];
#pragma unroll
            for (int j = 0; j < 4; j++) wr[j] = wsrc[(kc + 1) * 16 + j];
        }
        __syncthreads();

        const uint32_t* xb = sX + cb * 2304;
        const uint32_t* wb = sW2 + cb * 2 * 2304;
#pragma unroll
        for (int ks = 0; ks < 4; ks++) {
            const int kw = ks * 8 + (lane & 3);
            uint32_t a[2][4];
#pragma unroll
            for (int mt = 0; mt < 2; mt++) {
                int row = wm * 32 + mt * 16 + (lane >> 2);
                a[mt][0] = xb[row * 36 + kw];
                a[mt][1] = xb[(row + 8) * 36 + kw];
                a[mt][2] = xb[row * 36 + kw + 4];
                a[mt][3] = xb[(row + 8) * 36 + kw + 4];
            }
#pragma unroll
            for (int s = 0; s < 2; s++)
#pragma unroll
                for (int nt = 0; nt < 2; nt++) {
                    int n = wn * 16 + nt * 8 + (lane >> 2);
                    uint32_t b[2];
                    b[0] = wb[s * 2304 + n * 36 + kw];
                    b[1] = wb[s * 2304 + n * 36 + kw + 4];
#pragma unroll
                    for (int mt = 0; mt < 2; mt++)
                        mma_f16(acc[mt][nt], a[mt], b);
                }
        }

        if (kc < 31) {
            const int nb = cb ^ 1;
            uint32_t* xd = sX + nb * 2304 + lrow * 36 + lk8;
            xd[0] = xr0.x; xd[1] = xr0.y; xd[2] = xr0.z; xd[3] = xr0.w;
            xd[4] = xr1.x; xd[5] = xr1.y; xd[6] = xr1.z; xd[7] = xr1.w;
            const float* wf = (const float*)wr;
            uint32_t* w0d = sW2 + nb * 2 * 2304 + lrow * 36 + lk8;
            uint32_t* w1d = w0d + 2304;
#pragma unroll
            for (int j = 0; j < 8; j++) {
                float a = wf[2 * j], b = wf[2 * j + 1];
                __half ha = __float2half(a), hb = __float2half(b);
                w0d[j] = packh(ha, hb);
                w1d[j] = packh(__float2half(a - __half2float(ha)),
                               __float2half(b - __half2float(hb)));
            }
        }
    }

    float* outp = g_part + blockIdx.z * (1024 * 256);
    const int r0 = rowbase + wm * 32 + (lane >> 2);
    const int c0 = n0 + wn * 16 + (lane & 3) * 2;
#pragma unroll
    for (int mt = 0; mt < 2; mt++)
#pragma unroll
        for (int nt = 0; nt < 2; nt++) {
            int r = r0 + mt * 16, c = c0 + nt * 8;
            outp[r * 256 + c]           = acc[mt][nt][0];
            outp[r * 256 + c + 1]       = acc[mt][nt][1];
            outp[(r + 8) * 256 + c]     = acc[mt][nt][2];
            outp[(r + 8) * 256 + c + 1] = acc[mt][nt][3];
        }
}

// ---------------------------------------------------------------------------
// Kernel 4: 25-step LIF recurrence (R8 version — tensor-core layer-4 GEMV)
// ---------------------------------------------------------------------------
#define REC_SMEM_BYTES (36688 * 4)

__global__ void __launch_bounds__(1024, 1) rec_kernel(const float* __restrict__ w2,
                                                      const float* __restrict__ b2,
                                                      const float* __restrict__ w3,
                                                      const float* __restrict__ b3,
                                                      const float* __restrict__ b1,
                                                      float* __restrict__ out) {
    extern __shared__ uint32_t smu[];
    uint32_t* w4f   = smu;                          // 32768 u32: fc2_w frags
    float* w3s      = (float*)(smu + 32768);        // 1280
    float* b2s      = w3s + 1280;                   // 128
    float* b3s      = b2s + 128;                    // 16
    float* b1s      = b3s + 16;                     // 256
    __half* spk3h   = (__half*)(b1s + 256);         // 8 rows x 264 halves
    float* spk4s    = (float*)((uint32_t*)(b1s + 256) + 1056);  // 1024
    float* part5    = spk4s + 1024;                 // 160

    const int t = threadIdx.x;
    const int lane = t & 31, wid = t >> 5;
    const int rowbase = blockIdx.x * 8;

    for (int idx = t; idx < 32768; idx += 1024) {
        int reg = idx & 1, ln = (idx >> 1) & 31, s = (idx >> 6) & 1;
        int ks = (idx >> 7) & 15, w = idx >> 11;
        int n = w * 8 + (ln >> 2);
        int kb = ks * 16 + (ln & 3) * 2 + reg * 8;
        float w0 = w2[n * 256 + kb], w1v = w2[n * 256 + kb + 1];
        __half h0, h1;
        if (s == 0) { h0 = __float2half(w0); h1 = __float2half(w1v); }
        else {
            h0 = __float2half(w0 - __half2float(__float2half(w0)));
            h1 = __float2half(w1v - __half2float(__float2half(w1v)));
        }
        w4f[idx] = packh(h0, h1);
    }
    for (int idx = t; idx < 1280; idx += 1024) {
        int j = idx >> 7, k = idx & 127;
        w3s[k * 10 + j] = w3[idx];
    }
    if (t < 128) b2s[t] = b2[t];
    if (t < 10)  b3s[t] = b3[t];
    if (t < 256) b1s[t] = b1[t];
    __syncthreads();

    const int n3 = t & 255, rq = t >> 8;
    float mem3[2], c3[2];
    const int QS = 1024 * 256;
#pragma unroll
    for (int r = 0; r < 2; r++) {
        int row = rowbase + rq * 2 + r;
        mem3[r] = 0.f;
        int off = row * 256 + n3;
        c3[r] = ((g_part[off] + g_part[off + QS]) +
                 (g_part[off + 2 * QS] + g_part[off + 3 * QS])) + b1s[n3];
    }

    const int g4 = lane >> 2, q4 = lane & 3;
    float mem40 = 0.f, mem41 = 0.f;
    float b2v0 = 0.f, b2v1 = 0.f;
    if (wid < 16) {
        b2v0 = b2s[wid * 8 + q4 * 2];
        b2v1 = b2s[wid * 8 + q4 * 2 + 1];
    }
    float mem5 = 0.f;
    const int rj5 = t % 80, kh5 = (t < 80) ? 0 : 1;
    const int r5 = rj5 / 10, j5 = rj5 % 10;
    const float b3v = (t < 80) ? b3s[j5] : 0.f;

    for (int step = 0; step < NSTEPS; step++) {
#pragma unroll
        for (int r = 0; r < 2; r++) {
            float reset = (mem3[r] > 1.f) ? 1.f : 0.f;
            float m = 0.95f * mem3[r] + c3[r] - reset;
            mem3[r] = m;
            spk3h[(rq * 2 + r) * 264 + n3] = __float2half((m > 1.f) ? 1.f : 0.f);
        }
        __syncthreads();

        if (wid < 16) {
            float c[4] = {0.f, 0.f, 0.f, 0.f};
            uint32_t a[4];
            a[1] = 0u; a[3] = 0u;
            const __half* ab = spk3h + g4 * 264 + q4 * 2;
            const uint32_t* wb = w4f + wid * 2048;
#pragma unroll
            for (int ks = 0; ks < 16; ks++) {
                a[0] = *(const uint32_t*)(ab + ks * 16);
                a[2] = *(const uint32_t*)(ab + ks * 16 + 8);
                uint2 bv0 = *(const uint2*)(wb + ks * 128 + lane * 2);
                mma_f16(c, a, (const uint32_t*)&bv0);
                uint2 bv1 = *(const uint2*)(wb + ks * 128 + 64 + lane * 2);
                mma_f16(c, a, (const uint32_t*)&bv1);
            }
            float cur0 = c[0] + b2v0;
            float cur1 = c[1] + b2v1;
            float reset0 = (mem40 > 1.f) ? 1.f : 0.f;
            float m0 = 0.95f * mem40 + cur0 - reset0;
            mem40 = m0;
            float reset1 = (mem41 > 1.f) ? 1.f : 0.f;
            float m1 = 0.95f * mem41 + cur1 - reset1;
            mem41 = m1;
            int j0 = wid * 8 + q4 * 2;
            spk4s[j0 * 8 + g4]       = (m0 > 1.f) ? 1.f : 0.f;
            spk4s[(j0 + 1) * 8 + g4] = (m1 > 1.f) ? 1.f : 0.f;
        }
        __syncthreads();

        if (t < 160) {
            float a5 = 0.f;
            const int k0 = kh5 * 64;
#pragma unroll 8
            for (int k = k0; k < k0 + 64; k++)
                a5 += w3s[k * 10 + j5] * spk4s[k * 8 + r5];
            part5[kh5 * 80 + rj5] = a5;
        }
        __syncthreads();

        if (t < 80) {
            float a5 = b3v + (part5[t] + part5[80 + t]);
            float reset = (mem5 > 1.f) ? 1.f : 0.f;
            float m = 0.95f * mem5 + a5 - reset;
            mem5 = m;
            out[(step * 1024 + rowbase + r5) * 10 + j5] = (m > 1.f) ? 1.f : 0.f;
        }
    }
}

// ---------------------------------------------------------------------------
extern "C" void kernel_launch(void* const* d_in, const int* in_sizes, int n_in,
                              void* d_out, int out_size) {
    const float* x       = (const float*)d_in[0];
    const float* conv1_w = (const float*)d_in[1];
    const float* conv1_b = (const float*)d_in[2];
    const float* conv2_w = (const float*)d_in[3];
    const float* conv2_b = (const float*)d_in[4];
    const float* fc1_w   = (const float*)d_in[5];
    const float* fc1_b   = (const float*)d_in[6];
    const float* fc2_w   = (const float*)d_in[7];
    const float* fc2_b   = (const float*)d_in[8];
    const float* fc3_w   = (const float*)d_in[9];
    const float* fc3_b   = (const float*)d_in[10];
    float* out = (float*)d_out;

    cudaFuncSetAttribute(conv2_mma, cudaFuncAttributeMaxDynamicSharedMemorySize,
                         C2_SMEM);
    cudaFuncSetAttribute(fc1_mma, cudaFuncAttributeMaxDynamicSharedMemorySize,
                         FC1_SMEM);
    cudaFuncSetAttribute(rec_kernel, cudaFuncAttributeMaxDynamicSharedMemorySize,
                         REC_SMEM_BYTES);

    conv1_kernel<<<BATCH, 256>>>(x, conv1_w, conv1_b);
    conv2_mma<<<148, 512, C2_SMEM>>>(conv2_w, conv2_b);
    fc1_mma<<<dim3(16, 4, 4), 256, FC1_SMEM>>>(fc1_w);
    rec_kernel<<<128, 1024, REC_SMEM_BYTES>>>(fc2_w, fc2_b, fc3_w, fc3_b, fc1_b, out);
}

// round 10
// speedup vs baseline: 4.0045x; 1.2272x over previous
#include <cuda_runtime.h>
#include <cuda_fp16.h>
#include <cstdint>

#define BATCH 1024
#define NSTEPS 25

// scratch (device globals)
__device__ __half g_xh[BATCH * 8192];             // pooled spikes after conv2 (fp16, exact)
__device__ __half g_wh0[256 * 8192];              // fc1_w hi split
__device__ __half g_wh1[256 * 8192];              // fc1_w lo split
__device__ float  g_part[4 * 1024 * 256];         // fc1 K-split partials

// ---------------------------------------------------------------------------
// mma.sync m16n8k16 fp16 (baseline PTX)
// ---------------------------------------------------------------------------
__device__ __forceinline__ void mma_f16(float* d, const uint32_t* a, const uint32_t* b) {
    asm volatile(
        "mma.sync.aligned.m16n8k16.row.col.f32.f16.f16.f32 "
        "{%0,%1,%2,%3}, {%4,%5,%6,%7}, {%8,%9}, {%0,%1,%2,%3};"
        : "+f"(d[0]), "+f"(d[1]), "+f"(d[2]), "+f"(d[3])
        : "r"(a[0]), "r"(a[1]), "r"(a[2]), "r"(a[3]), "r"(b[0]), "r"(b[1]));
}
__device__ __forceinline__ uint32_t packh(__half a, __half b) {
    return (uint32_t)__half_as_ushort(a) | ((uint32_t)__half_as_ushort(b) << 16);
}

// ---------------------------------------------------------------------------
// Kernel A: split fc1_w into 2 fp16 planes (once)
// ---------------------------------------------------------------------------
__global__ void __launch_bounds__(256) wprep_kernel(const float* __restrict__ W) {
    int i = blockIdx.x * 256 + threadIdx.x;
    if (i < 256 * 8192) {
        float w = W[i];
        __half h0 = __float2half(w);
        g_wh0[i] = h0;
        g_wh1[i] = __float2half(w - __half2float(h0));
    }
}

// ---------------------------------------------------------------------------
// Kernel B: FUSED conv1 (scalar fp32) + conv2 (mma fp16 2-split) per image.
//   conv1 writes pooled fp16 spikes directly into the interleaved conv2
//   staging buffer — no g_c1 gmem round-trip, no separate kernel.
//   512 threads / 16 warps; warp grid wm(2) x wn(8) for conv2.
// ---------------------------------------------------------------------------
#define C2_AF_OFF   0
#define C2_AF_BYTES 73728                     // 2*4*18*128 u32
#define C2_IN_OFF   73728
#define C2_IN_BYTES (34 * 18 * 48 * 2)        // 58752
#define C2_X1_OFF   (C2_IN_OFF + C2_IN_BYTES)         // 132480
#define C2_X1_BYTES (66 * 34 * 4)                     // 8976
#define C2_W1_OFF   (C2_X1_OFF + C2_X1_BYTES)         // 141456
#define C2_SMEM     (C2_W1_OFF + 320 * 4)             // 142736

__global__ void __launch_bounds__(512, 1) conv12_mma(const float* __restrict__ x,
                                                     const float* __restrict__ w1,
                                                     const float* __restrict__ b1,
                                                     const float* __restrict__ w2,
                                                     const float* __restrict__ b2) {
    extern __shared__ char sm[];
    uint32_t* sAf = (uint32_t*)(sm + C2_AF_OFF);
    __half* sIn = (__half*)(sm + C2_IN_OFF);
    float* sX1 = (float*)(sm + C2_X1_OFF);
    float* sW1 = (float*)(sm + C2_W1_OFF);      // 288 w + 32 bias

    const int t = threadIdx.x;
    const int lane = t & 31, wid = t >> 5;
    const int wm = wid & 1, wn = wid >> 1;

    // zero staging buffers (halos persist as zero)
    for (int i = t; i < C2_IN_BYTES / 4; i += 512) ((uint32_t*)sIn)[i] = 0u;
    for (int i = t; i < 66 * 34; i += 512) sX1[i] = 0.f;
    for (int i = t; i < 288; i += 512) sW1[i] = w1[i];
    if (t < 32) sW1[288 + t] = b1[t];

    // conv2 weight fragments, 2 fp16 splits, K order (tap, ci)
    for (int idx = t; idx < 4 * 18 * 32 * 4; idx += 512) {
        int r = idx & 3, ln = (idx >> 2) & 31, ks = (idx >> 7) % 18, mt = idx / (128 * 18);
        int oc = mt * 16 + (ln >> 2) + (r & 1) * 8;
        int kk = (ln & 3) * 2 + (r >> 1) * 8;
        int tap = ks >> 1, ci0 = (ks & 1) * 16;
        float w0 = w2[oc * 288 + (ci0 + kk) * 9 + tap];
        float w1v = w2[oc * 288 + (ci0 + kk + 1) * 9 + tap];
#pragma unroll
        for (int s = 0; s < 2; s++) {
            __half h0 = __float2half(w0);
            __half h1 = __float2half(w1v);
            w0 -= __half2float(h0);
            w1v -= __half2float(h1);
            sAf[((s * 4 + mt) * 18 + ks) * 128 + ln * 4 + r] = packh(h0, h1);
        }
    }

    float biasr[2][2];
#pragma unroll
    for (int ml = 0; ml < 2; ml++) {
        int mt = wm * 2 + ml;
        biasr[ml][0] = b2[mt * 16 + (lane >> 2)];
        biasr[ml][1] = b2[mt * 16 + (lane >> 2) + 8];
    }

    int posoff[8];
#pragma unroll
    for (int nt = 0; nt < 8; nt++) {
        int pos = wn * 64 + nt * 8 + (lane >> 2);
        posoff[nt] = ((pos >> 4) * 18 + (pos & 15)) * 48;
    }

    // conv1 cell for this thread: ph in [0,32), pw in [0,16)
    const int ph1 = t >> 4, pw1 = t & 15;
    const int sInCellBase = ((ph1 + 1) * 18 + (pw1 + 1)) * 48;

    __syncthreads();

    for (int img = blockIdx.x; img < BATCH; img += gridDim.x) {
        // ---- stage raw input x (fp32, 64x32) into padded sX1 ----
        const float* xi = x + img * 2048;
        {
            float4 v = ((const float4*)xi)[t];       // elements 4t..4t+3
            int y = t >> 3, xc = (t & 7) * 4;
            float* p = sX1 + (y + 1) * 34 + xc + 1;
            p[0] = v.x; p[1] = v.y; p[2] = v.z; p[3] = v.w;
        }
        __syncthreads();

        // ---- conv1 + spike + pool, write fp16 into interleaved sIn ----
        {
            float in[4][4];
#pragma unroll
            for (int r = 0; r < 4; r++)
#pragma unroll
                for (int c = 0; c < 4; c++)
                    in[r][c] = sX1[(2 * ph1 + r) * 34 + (2 * pw1 + c)];

#pragma unroll 4
            for (int ch = 0; ch < 32; ch++) {
                float wv[9];
#pragma unroll
                for (int k = 0; k < 9; k++) wv[k] = sW1[ch * 9 + k];
                float bb = sW1[288 + ch];
                float cnt = 0.f;
#pragma unroll
                for (int dy = 0; dy < 2; dy++)
#pragma unroll
                    for (int dx = 0; dx < 2; dx++) {
                        float s = bb;
#pragma unroll
                        for (int ky = 0; ky < 3; ky++)
#pragma unroll
                            for (int kx = 0; kx < 3; kx++)
                                s += wv[ky * 3 + kx] * in[dy + ky][dx + kx];
                        cnt += (s > 1.f) ? 1.f : 0.f;
                    }
                int np = (ch & 16) + ((ch & 6) << 1) + (ch & 1) + (((ch >> 3) & 1) << 1);
                sIn[sInCellBase + np] = __float2half(cnt * 0.25f);
            }
        }
        __syncthreads();

        // ---- conv2 mainloop (mma fp16 2-split) ----
        float acc[2][8][4];
#pragma unroll
        for (int ml = 0; ml < 2; ml++)
#pragma unroll
            for (int nt = 0; nt < 8; nt++)
#pragma unroll
                for (int q = 0; q < 4; q++) acc[ml][nt][q] = 0.f;

#pragma unroll 2
        for (int ks = 0; ks < 18; ks++) {
            int tap = ks >> 1, ci0 = (ks & 1) * 16;
            int dy = tap / 3, dx = tap - dy * 3;
            int toff = (dy * 18 + dx) * 48 + ci0 + (lane & 3) * 4;

            uint32_t bfr[8][2];
#pragma unroll
            for (int nt = 0; nt < 8; nt++) {
                uint2 bv = *(const uint2*)(sIn + posoff[nt] + toff);
                bfr[nt][0] = bv.x; bfr[nt][1] = bv.y;
            }
#pragma unroll
            for (int s = 0; s < 2; s++)
#pragma unroll
                for (int ml = 0; ml < 2; ml++) {
                    int mt = wm * 2 + ml;
                    uint4 av = ((const uint4*)(sAf + ((s * 4 + mt) * 18 + ks) * 128))[lane];
                    uint32_t a[4] = {av.x, av.y, av.z, av.w};
#pragma unroll
                    for (int nt = 0; nt < 8; nt++)
                        mma_f16(acc[ml][nt], a, bfr[nt]);
                }
        }

        // ---- epilogue: +bias, spike, in-thread 2x2 pool ----
        __half* xout = g_xh + img * 8192;
#pragma unroll
        for (int ml = 0; ml < 2; ml++)
#pragma unroll
            for (int rh = 0; rh < 2; rh++) {
                int ch = (wm * 2 + ml) * 16 + (lane >> 2) + rh * 8;
                float bv = biasr[ml][rh];
#pragma unroll
                for (int np2 = 0; np2 < 4; np2++) {
                    int nt = (np2 & 1) + (np2 >> 1) * 4;   // {0,1,4,5}
                    float s0 = (acc[ml][nt][rh * 2]         + bv > 1.f) ? 1.f : 0.f;
                    float s1 = (acc[ml][nt][rh * 2 + 1]     + bv > 1.f) ? 1.f : 0.f;
                    float s2 = (acc[ml][nt + 2][rh * 2]     + bv > 1.f) ? 1.f : 0.f;
                    float s3 = (acc[ml][nt + 2][rh * 2 + 1] + bv > 1.f) ? 1.f : 0.f;
                    int h = wn * 4 + (nt >> 1);
                    int ph = h >> 1;
                    int pw = (nt & 1) * 4 + (lane & 3);
                    xout[ch * 128 + ph * 8 + pw] = __float2half((s0 + s1 + s2 + s3) * 0.25f);
                }
            }
        __syncthreads();   // sIn/sX1 free for next image
    }
}

// ---------------------------------------------------------------------------
// Kernel 3: fc1 via mma.sync fp16 (pre-split planes), split-K=4, dbl-buffer.
// ---------------------------------------------------------------------------
#define FC1_SMEM ((2 * 2304 + 4 * 2304) * 4)   // 55296 B

__global__ void __launch_bounds__(256) fc1_mma() {
    extern __shared__ uint32_t smf[];
    uint32_t* sX = smf;                    // [buf][64*36]
    uint32_t* sW2 = smf + 2 * 2304;        // [buf][split][64*36]

    const int t = threadIdx.x;
    const int lane = t & 31, wid = t >> 5;
    const int wm = wid & 1, wn = wid >> 1;
    const int rowbase = blockIdx.x * 64;
    const int n0 = blockIdx.y * 64;
    const int k0 = blockIdx.z * 2048;

    const int lrow = t >> 2, lk16 = (t & 3) * 16, lk8 = (t & 3) * 8;

    const uint4* xsrc  = (const uint4*)(g_xh  + (rowbase + lrow) * 8192 + k0 + lk16);
    const uint4* w0src = (const uint4*)(g_wh0 + (n0 + lrow) * 8192 + k0 + lk16);
    const uint4* w1src = (const uint4*)(g_wh1 + (n0 + lrow) * 8192 + k0 + lk16);

    float acc[2][2][4];
#pragma unroll
    for (int mt = 0; mt < 2; mt++)
#pragma unroll
        for (int nt = 0; nt < 2; nt++)
#pragma unroll
            for (int q = 0; q < 4; q++) acc[mt][nt][q] = 0.f;

    uint4 xr0, xr1, wa0, wa1, wb0, wb1;
    xr0 = xsrc[0];  xr1 = xsrc[1];
    wa0 = w0src[0]; wa1 = w0src[1];
    wb0 = w1src[0]; wb1 = w1src[1];

    // prologue store into buf 0
    {
        uint32_t* xd = sX + lrow * 36 + lk8;
        xd[0] = xr0.x; xd[1] = xr0.y; xd[2] = xr0.z; xd[3] = xr0.w;
        xd[4] = xr1.x; xd[5] = xr1.y; xd[6] = xr1.z; xd[7] = xr1.w;
        uint32_t* w0d = sW2 + lrow * 36 + lk8;
        w0d[0] = wa0.x; w0d[1] = wa0.y; w0d[2] = wa0.z; w0d[3] = wa0.w;
        w0d[4] = wa1.x; w0d[5] = wa1.y; w0d[6] = wa1.z; w0d[7] = wa1.w;
        uint32_t* w1d = sW2 + 2304 + lrow * 36 + lk8;
        w1d[0] = wb0.x; w1d[1] = wb0.y; w1d[2] = wb0.z; w1d[3] = wb0.w;
        w1d[4] = wb1.x; w1d[5] = wb1.y; w1d[6] = wb1.z; w1d[7] = wb1.w;
    }

    for (int kc = 0; kc < 32; kc++) {
        const int cb = kc & 1;
        if (kc < 31) {
            xr0 = xsrc[(kc + 1) * 8];  xr1 = xsrc[(kc + 1) * 8 + 1];
            wa0 = w0src[(kc + 1) * 8]; wa1 = w0src[(kc + 1) * 8 + 1];
            wb0 = w1src[(kc + 1) * 8]; wb1 = w1src[(kc + 1) * 8 + 1];
        }
        __syncthreads();

        const uint32_t* xb = sX + cb * 2304;
        const uint32_t* wb = sW2 + cb * 2 * 2304;
#pragma unroll
        for (int ks = 0; ks < 4; ks++) {
            const int kw = ks * 8 + (lane & 3);
            uint32_t a[2][4];
#pragma unroll
            for (int mt = 0; mt < 2; mt++) {
                int row = wm * 32 + mt * 16 + (lane >> 2);
                a[mt][0] = xb[row * 36 + kw];
                a[mt][1] = xb[(row + 8) * 36 + kw];
                a[mt][2] = xb[row * 36 + kw + 4];
                a[mt][3] = xb[(row + 8) * 36 + kw + 4];
            }
#pragma unroll
            for (int s = 0; s < 2; s++)
#pragma unroll
                for (int nt = 0; nt < 2; nt++) {
                    int n = wn * 16 + nt * 8 + (lane >> 2);
                    uint32_t b[2];
                    b[0] = wb[s * 2304 + n * 36 + kw];
                    b[1] = wb[s * 2304 + n * 36 + kw + 4];
#pragma unroll
                    for (int mt = 0; mt < 2; mt++)
                        mma_f16(acc[mt][nt], a[mt], b);
                }
        }

        if (kc < 31) {
            const int nb = cb ^ 1;
            uint32_t* xd = sX + nb * 2304 + lrow * 36 + lk8;
            xd[0] = xr0.x; xd[1] = xr0.y; xd[2] = xr0.z; xd[3] = xr0.w;
            xd[4] = xr1.x; xd[5] = xr1.y; xd[6] = xr1.z; xd[7] = xr1.w;
            uint32_t* w0d = sW2 + nb * 2 * 2304 + lrow * 36 + lk8;
            w0d[0] = wa0.x; w0d[1] = wa0.y; w0d[2] = wa0.z; w0d[3] = wa0.w;
            w0d[4] = wa1.x; w0d[5] = wa1.y; w0d[6] = wa1.z; w0d[7] = wa1.w;
            uint32_t* w1d = w0d + 2304;
            w1d[0] = wb0.x; w1d[1] = wb0.y; w1d[2] = wb0.z; w1d[3] = wb0.w;
            w1d[4] = wb1.x; w1d[5] = wb1.y; w1d[6] = wb1.z; w1d[7] = wb1.w;
        }
    }

    float* outp = g_part + blockIdx.z * (1024 * 256);
    const int r0 = rowbase + wm * 32 + (lane >> 2);
    const int c0 = n0 + wn * 16 + (lane & 3) * 2;
#pragma unroll
    for (int mt = 0; mt < 2; mt++)
#pragma unroll
        for (int nt = 0; nt < 2; nt++) {
            int r = r0 + mt * 16, c = c0 + nt * 8;
            outp[r * 256 + c]           = acc[mt][nt][0];
            outp[r * 256 + c + 1]       = acc[mt][nt][1];
            outp[(r + 8) * 256 + c]     = acc[mt][nt][2];
            outp[(r + 8) * 256 + c + 1] = acc[mt][nt][3];
        }
}

// ---------------------------------------------------------------------------
// Kernel 4: 25-step LIF recurrence (R8/R9 version — tensor-core layer-4 GEMV)
// ---------------------------------------------------------------------------
#define REC_SMEM_BYTES (36688 * 4)

__global__ void __launch_bounds__(1024, 1) rec_kernel(const float* __restrict__ w2,
                                                      const float* __restrict__ b2,
                                                      const float* __restrict__ w3,
                                                      const float* __restrict__ b3,
                                                      const float* __restrict__ b1,
                                                      float* __restrict__ out) {
    extern __shared__ uint32_t smu[];
    uint32_t* w4f   = smu;                          // 32768 u32: fc2_w frags
    float* w3s      = (float*)(smu + 32768);        // 1280
    float* b2s      = w3s + 1280;                   // 128
    float* b3s      = b2s + 128;                    // 16
    float* b1s      = b3s + 16;                     // 256
    __half* spk3h   = (__half*)(b1s + 256);         // 8 rows x 264 halves
    float* spk4s    = (float*)((uint32_t*)(b1s + 256) + 1056);  // 1024
    float* part5    = spk4s + 1024;                 // 160

    const int t = threadIdx.x;
    const int lane = t & 31, wid = t >> 5;
    const int rowbase = blockIdx.x * 8;

    for (int idx = t; idx < 32768; idx += 1024) {
        int reg = idx & 1, ln = (idx >> 1) & 31, s = (idx >> 6) & 1;
        int ks = (idx >> 7) & 15, w = idx >> 11;
        int n = w * 8 + (ln >> 2);
        int kb = ks * 16 + (ln & 3) * 2 + reg * 8;
        float w0 = w2[n * 256 + kb], w1v = w2[n * 256 + kb + 1];
        __half h0, h1;
        if (s == 0) { h0 = __float2half(w0); h1 = __float2half(w1v); }
        else {
            h0 = __float2half(w0 - __half2float(__float2half(w0)));
            h1 = __float2half(w1v - __half2float(__float2half(w1v)));
        }
        w4f[idx] = packh(h0, h1);
    }
    for (int idx = t; idx < 1280; idx += 1024) {
        int j = idx >> 7, k = idx & 127;
        w3s[k * 10 + j] = w3[idx];
    }
    if (t < 128) b2s[t] = b2[t];
    if (t < 10)  b3s[t] = b3[t];
    if (t < 256) b1s[t] = b1[t];
    __syncthreads();

    const int n3 = t & 255, rq = t >> 8;
    float mem3[2], c3[2];
    const int QS = 1024 * 256;
#pragma unroll
    for (int r = 0; r < 2; r++) {
        int row = rowbase + rq * 2 + r;
        mem3[r] = 0.f;
        int off = row * 256 + n3;
        c3[r] = ((g_part[off] + g_part[off + QS]) +
                 (g_part[off + 2 * QS] + g_part[off + 3 * QS])) + b1s[n3];
    }

    const int g4 = lane >> 2, q4 = lane & 3;
    float mem40 = 0.f, mem41 = 0.f;
    float b2v0 = 0.f, b2v1 = 0.f;
    if (wid < 16) {
        b2v0 = b2s[wid * 8 + q4 * 2];
        b2v1 = b2s[wid * 8 + q4 * 2 + 1];
    }
    float mem5 = 0.f;
    const int rj5 = t % 80, kh5 = (t < 80) ? 0 : 1;
    const int r5 = rj5 / 10, j5 = rj5 % 10;
    const float b3v = (t < 80) ? b3s[j5] : 0.f;

    for (int step = 0; step < NSTEPS; step++) {
#pragma unroll
        for (int r = 0; r < 2; r++) {
            float reset = (mem3[r] > 1.f) ? 1.f : 0.f;
            float m = 0.95f * mem3[r] + c3[r] - reset;
            mem3[r] = m;
            spk3h[(rq * 2 + r) * 264 + n3] = __float2half((m > 1.f) ? 1.f : 0.f);
        }
        __syncthreads();

        if (wid < 16) {
            float c[4] = {0.f, 0.f, 0.f, 0.f};
            uint32_t a[4];
            a[1] = 0u; a[3] = 0u;
            const __half* ab = spk3h + g4 * 264 + q4 * 2;
            const uint32_t* wb = w4f + wid * 2048;
#pragma unroll
            for (int ks = 0; ks < 16; ks++) {
                a[0] = *(const uint32_t*)(ab + ks * 16);
                a[2] = *(const uint32_t*)(ab + ks * 16 + 8);
                uint2 bv0 = *(const uint2*)(wb + ks * 128 + lane * 2);
                mma_f16(c, a, (const uint32_t*)&bv0);
                uint2 bv1 = *(const uint2*)(wb + ks * 128 + 64 + lane * 2);
                mma_f16(c, a, (const uint32_t*)&bv1);
            }
            float cur0 = c[0] + b2v0;
            float cur1 = c[1] + b2v1;
            float reset0 = (mem40 > 1.f) ? 1.f : 0.f;
            float m0 = 0.95f * mem40 + cur0 - reset0;
            mem40 = m0;
            float reset1 = (mem41 > 1.f) ? 1.f : 0.f;
            float m1 = 0.95f * mem41 + cur1 - reset1;
            mem41 = m1;
            int j0 = wid * 8 + q4 * 2;
            spk4s[j0 * 8 + g4]       = (m0 > 1.f) ? 1.f : 0.f;
            spk4s[(j0 + 1) * 8 + g4] = (m1 > 1.f) ? 1.f : 0.f;
        }
        __syncthreads();

        if (t < 160) {
            float a5 = 0.f;
            const int k0 = kh5 * 64;
#pragma unroll 8
            for (int k = k0; k < k0 + 64; k++)
                a5 += w3s[k * 10 + j5] * spk4s[k * 8 + r5];
            part5[kh5 * 80 + rj5] = a5;
        }
        __syncthreads();

        if (t < 80) {
            float a5 = b3v + (part5[t] + part5[80 + t]);
            float reset = (mem5 > 1.f) ? 1.f : 0.f;
            float m = 0.95f * mem5 + a5 - reset;
            mem5 = m;
            out[(step * 1024 + rowbase + r5) * 10 + j5] = (m > 1.f) ? 1.f : 0.f;
        }
    }
}

// ---------------------------------------------------------------------------
extern "C" void kernel_launch(void* const* d_in, const int* in_sizes, int n_in,
                              void* d_out, int out_size) {
    const float* x       = (const float*)d_in[0];
    const float* conv1_w = (const float*)d_in[1];
    const float* conv1_b = (const float*)d_in[2];
    const float* conv2_w = (const float*)d_in[3];
    const float* conv2_b = (const float*)d_in[4];
    const float* fc1_w   = (const float*)d_in[5];
    const float* fc1_b   = (const float*)d_in[6];
    const float* fc2_w   = (const float*)d_in[7];
    const float* fc2_b   = (const float*)d_in[8];
    const float* fc3_w   = (const float*)d_in[9];
    const float* fc3_b   = (const float*)d_in[10];
    float* out = (float*)d_out;

    cudaFuncSetAttribute(conv12_mma, cudaFuncAttributeMaxDynamicSharedMemorySize,
                         C2_SMEM);
    cudaFuncSetAttribute(fc1_mma, cudaFuncAttributeMaxDynamicSharedMemorySize,
                         FC1_SMEM);
    cudaFuncSetAttribute(rec_kernel, cudaFuncAttributeMaxDynamicSharedMemorySize,
                         REC_SMEM_BYTES);

    wprep_kernel<<<8192, 256>>>(fc1_w);
    conv12_mma<<<148, 512, C2_SMEM>>>(x, conv1_w, conv1_b, conv2_w, conv2_b);
    fc1_mma<<<dim3(16, 4, 4), 256, FC1_SMEM>>>();
    rec_kernel<<<128, 1024, REC_SMEM_BYTES>>>(fc2_w, fc2_b, fc3_w, fc3_b, fc1_b, out);
}